// round 1
// baseline (speedup 1.0000x reference)
#include <cuda_runtime.h>
#include <math.h>
#include <stddef.h>

// ---------------- problem constants ----------------
#define BB     2
#define SS     2048
#define DIMM   2048
#define HEADS  16
#define HD     128
#define FFN    8192
#define CTX    512
#define M1     (BB*SS)        // 4096
#define MC     (BB*CTX)       // 1024
#define EMSTR  (6*DIMM)       // 12288, per-batch stride in em
#define EPSF   1e-6f

// ---------------- device scratch ----------------
__device__ float g_em [BB*6*DIMM];
__device__ float g_cos[SS*(HD/2)];
__device__ float g_sin[SS*(HD/2)];
__device__ float g_x  [M1*DIMM];
__device__ float g_xn [M1*DIMM];
__device__ float g_tmp[M1*DIMM];
__device__ float g_q  [BB*HEADS*SS*HD];
__device__ float g_k  [BB*HEADS*SS*HD];
__device__ float g_v  [M1*DIMM];
__device__ float g_y  [M1*DIMM];
__device__ float g_h  [(size_t)M1*FFN];

// ---------------- small kernels ----------------
__global__ void k_embed(const float* __restrict__ mo, const float* __restrict__ e,
                        float* __restrict__ em) {
    int i = blockIdx.x*256 + threadIdx.x;
    if (i < BB*6*DIMM) em[i] = mo[i % EMSTR] + e[i];
}

__global__ void k_ropetab(const float* __restrict__ fc, const float* __restrict__ fs,
                          float* __restrict__ cb, float* __restrict__ sb) {
    int i = blockIdx.x*256 + threadIdx.x;
    if (i >= SS*64) return;
    int s = i >> 6, d = i & 63;
    int f = s >> 8, h = (s >> 4) & 15, w = s & 15;
    int row = (d < 22) ? f : ((d < 43) ? h : w);
    cb[i] = fc[row*64 + d];
    sb[i] = fs[row*64 + d];
}

// LayerNorm: out = ln(x)*sc + sh. em_mode=1: sc=1+scv[b*EMSTR+c], sh=shv[b*EMSTR+c]
__global__ void k_ln(const float* __restrict__ x, const float* __restrict__ scv,
                     const float* __restrict__ shv, int em_mode, float* __restrict__ out) {
    __shared__ float buf[DIMM];
    __shared__ float red[256];
    __shared__ float s_m, s_inv;
    int row = blockIdx.x, tid = threadIdx.x;
    const float* xr = x + (size_t)row*DIMM;
    float ls = 0.f;
    for (int c = tid; c < DIMM; c += 256) { float v = xr[c]; buf[c] = v; ls += v; }
    red[tid] = ls; __syncthreads();
    for (int s2 = 128; s2 > 0; s2 >>= 1) { if (tid < s2) red[tid] += red[tid+s2]; __syncthreads(); }
    if (tid == 0) s_m = red[0] * (1.f/DIMM);
    __syncthreads();
    float m = s_m, lv = 0.f;
    for (int c = tid; c < DIMM; c += 256) { float d = buf[c]-m; lv += d*d; }
    red[tid] = lv; __syncthreads();
    for (int s2 = 128; s2 > 0; s2 >>= 1) { if (tid < s2) red[tid] += red[tid+s2]; __syncthreads(); }
    if (tid == 0) s_inv = rsqrtf(red[0]*(1.f/DIMM) + EPSF);
    __syncthreads();
    float inv = s_inv;
    int bo = (row >> 11) * EMSTR;
    float* orow = out + (size_t)row*DIMM;
    for (int c = tid; c < DIMM; c += 256) {
        float sc, sh;
        if (em_mode) { sc = 1.f + scv[bo+c]; sh = shv[bo+c]; }
        else         { sc = scv[c];          sh = shv[c];    }
        orow[c] = (buf[c]-m)*inv*sc + sh;
    }
}

// RMS norm + (optional RoPE) + transpose to [B, H, L, HD]. rows = B*L.
__global__ void k_rms_t(const float* __restrict__ in, const float* __restrict__ w,
                        float* __restrict__ outT, int L, int do_rope) {
    __shared__ float buf[DIMM];
    __shared__ float red[256];
    __shared__ float s_inv;
    int row = blockIdx.x, tid = threadIdx.x;
    int b = row / L, s = row % L;
    const float* xr = in + (size_t)row*DIMM;
    float ls = 0.f;
    for (int c = tid; c < DIMM; c += 256) { float v = xr[c]; buf[c] = v; ls += v*v; }
    red[tid] = ls; __syncthreads();
    for (int s2 = 128; s2 > 0; s2 >>= 1) { if (tid < s2) red[tid] += red[tid+s2]; __syncthreads(); }
    if (tid == 0) s_inv = rsqrtf(red[0]*(1.f/DIMM) + EPSF);
    __syncthreads();
    float inv = s_inv;
    if (do_rope) {
        for (int p = tid; p < DIMM/2; p += 256) {
            int hh = p >> 6, i = p & 63;
            float vr = buf[2*p]   * w[2*p]   * inv;
            float vi = buf[2*p+1] * w[2*p+1] * inv;
            float c = g_cos[s*64 + i], sn = g_sin[s*64 + i];
            size_t base = ((size_t)(b*HEADS + hh)*L + s) * HD;
            outT[base + 2*i]   = vr*c - vi*sn;
            outT[base + 2*i+1] = vr*sn + vi*c;
        }
    } else {
        for (int d = tid; d < DIMM; d += 256) {
            int hh = d >> 7, hd = d & 127;
            outT[((size_t)(b*HEADS + hh)*L + s)*HD + hd] = buf[d]*inv*w[d];
        }
    }
}

// ---------------- SGEMM 128x128x8, double-buffered ----------------
// C[M,N] = A[M,K] @ W[K,N] + bias, with epilogues:
// EPI 0: +bias  1: gelu(+bias)  2: res + (+bias)  3: res + (+bias)*gate[b,c]
template<int EPI>
__global__ __launch_bounds__(256)
void k_gemm(const float* __restrict__ A, const float* __restrict__ W,
            const float* __restrict__ bias, const float* __restrict__ res,
            const float* __restrict__ gate, float* __restrict__ C,
            int M, int N, int K) {
    __shared__ __align__(16) float As[2][8][128];
    __shared__ __align__(16) float Bs[2][8][128];
    int tid = threadIdx.x;
    int tx = tid & 15, ty = tid >> 4;
    int bm = blockIdx.y << 7, bn = blockIdx.x << 7;
    int a_m = tid >> 1,  a_k = (tid & 1) << 2;
    int b_k = tid >> 5,  b_n = (tid & 31) << 2;
    const float* Ap = A + (size_t)(bm + a_m)*K + a_k;
    const float* Bp = W + (size_t)b_k*N + bn + b_n;

    float acc[8][8];
#pragma unroll
    for (int i = 0; i < 8; i++)
#pragma unroll
        for (int j = 0; j < 8; j++) acc[i][j] = 0.f;

    {   // prologue: stage 0
        float4 av = *(const float4*)Ap;
        As[0][a_k+0][a_m] = av.x; As[0][a_k+1][a_m] = av.y;
        As[0][a_k+2][a_m] = av.z; As[0][a_k+3][a_m] = av.w;
        *(float4*)&Bs[0][b_k][b_n] = *(const float4*)Bp;
    }
    __syncthreads();
    int nk = K >> 3;
    for (int kt = 0; kt < nk; kt++) {
        int st = kt & 1;
        if (kt + 1 < nk) {
            float4 av = *(const float4*)(Ap + (size_t)(kt+1)*8);
            float4 bv = *(const float4*)(Bp + (size_t)(kt+1)*8*N);
            As[st^1][a_k+0][a_m] = av.x; As[st^1][a_k+1][a_m] = av.y;
            As[st^1][a_k+2][a_m] = av.z; As[st^1][a_k+3][a_m] = av.w;
            *(float4*)&Bs[st^1][b_k][b_n] = bv;
        }
#pragma unroll
        for (int k = 0; k < 8; k++) {
            float a[8], b[8];
            *(float4*)(a)   = *(float4*)&As[st][k][ty<<2];
            *(float4*)(a+4) = *(float4*)&As[st][k][64 + (ty<<2)];
            *(float4*)(b)   = *(float4*)&Bs[st][k][tx<<2];
            *(float4*)(b+4) = *(float4*)&Bs[st][k][64 + (tx<<2)];
#pragma unroll
            for (int i = 0; i < 8; i++)
#pragma unroll
                for (int j = 0; j < 8; j++) acc[i][j] += a[i]*b[j];
        }
        __syncthreads();
    }

#pragma unroll
    for (int i = 0; i < 8; i++) {
        int r = bm + ((i < 4) ? (ty*4 + i) : (64 + ty*4 + (i-4)));
        int bidx = r >> 11;  // rows-per-batch = 2048 (only used when M==4096)
#pragma unroll
        for (int j = 0; j < 8; j++) {
            int c = bn + ((j < 4) ? (tx*4 + j) : (64 + tx*4 + (j-4)));
            float v = acc[i][j] + bias[c];
            if (EPI == 1) {
                float u = v;
                v = 0.5f*u*(1.f + tanhf(0.7978845608028654f*(u + 0.044715f*u*u*u)));
            }
            if (EPI == 2) v += res[(size_t)r*N + c];
            if (EPI == 3) v = res[(size_t)r*N + c] + v * gate[bidx*EMSTR + c];
            C[(size_t)r*N + c] = v;
        }
    }
}

// ---------------- flash attention (fp32) ----------------
// q/k in [B,H,L,HD] (k: L=Lk), v in [B,Lk,DIM], out y in [B,2048,DIM]
#define ATTN_SMEM ((64*132*2 + 64*68 + 192)*4)
__global__ __launch_bounds__(256)
void k_attn(const float* __restrict__ qt, const float* __restrict__ ktp,
            const float* __restrict__ v, float* __restrict__ y, int Lk) {
    extern __shared__ float smem[];
    float* q_s  = smem;                 // 64*132
    float* kv_s = q_s + 64*132;         // 64*132
    float* p_s  = kv_s + 64*132;        // 64*68
    float* m_s  = p_s + 64*68;
    float* l_s  = m_s + 64;
    float* sc_s = l_s + 64;

    int tid = threadIdx.x;
    int qtile = blockIdx.x, hh = blockIdx.y, b = blockIdx.z;
    const float* qb = qt + ((size_t)(b*HEADS + hh)*SS + qtile*64) * HD;
    const float* kb = ktp + (size_t)(b*HEADS + hh)*Lk*HD;
    const float* vb = v + (size_t)b*Lk*DIMM + hh*HD;

    for (int idx = tid*4; idx < 64*128; idx += 1024) {
        int r = idx >> 7, d = idx & 127;
        *(float4*)&q_s[r*132 + d] = *(const float4*)&qb[r*128 + d];
    }
    if (tid < 64) { m_s[tid] = -1e30f; l_s[tid] = 0.f; }

    float acc[4][8];
#pragma unroll
    for (int i = 0; i < 4; i++)
#pragma unroll
        for (int j = 0; j < 8; j++) acc[i][j] = 0.f;

    int rowg = tid >> 4, colg = tid & 15;
    const float scale = 0.08838834764831845f;   // 1/sqrt(128)

    int ntiles = Lk >> 6;
    for (int kt2 = 0; kt2 < ntiles; kt2++) {
        __syncthreads();
        for (int idx = tid*4; idx < 8192; idx += 1024) {
            int r = idx >> 7, d = idx & 127;
            *(float4*)&kv_s[r*132 + d] = *(const float4*)&kb[(size_t)(kt2*64 + r)*128 + d];
        }
        __syncthreads();
        // S = Q @ K^T (64x64), thread: rows rowg*4+i, cols colg+16j (j<4)
        float sacc[4][4];
#pragma unroll
        for (int i = 0; i < 4; i++)
#pragma unroll
            for (int j = 0; j < 4; j++) sacc[i][j] = 0.f;
#pragma unroll 4
        for (int k = 0; k < 128; k++) {
            float a0 = q_s[(rowg*4+0)*132 + k];
            float a1 = q_s[(rowg*4+1)*132 + k];
            float a2 = q_s[(rowg*4+2)*132 + k];
            float a3 = q_s[(rowg*4+3)*132 + k];
            float b0 = kv_s[(colg+ 0)*132 + k];
            float b1 = kv_s[(colg+16)*132 + k];
            float b2 = kv_s[(colg+32)*132 + k];
            float b3 = kv_s[(colg+48)*132 + k];
            sacc[0][0] += a0*b0; sacc[0][1] += a0*b1; sacc[0][2] += a0*b2; sacc[0][3] += a0*b3;
            sacc[1][0] += a1*b0; sacc[1][1] += a1*b1; sacc[1][2] += a1*b2; sacc[1][3] += a1*b3;
            sacc[2][0] += a2*b0; sacc[2][1] += a2*b1; sacc[2][2] += a2*b2; sacc[2][3] += a2*b3;
            sacc[3][0] += a3*b0; sacc[3][1] += a3*b1; sacc[3][2] += a3*b2; sacc[3][3] += a3*b3;
        }
#pragma unroll
        for (int i = 0; i < 4; i++)
#pragma unroll
            for (int j = 0; j < 4; j++)
                p_s[(rowg*4+i)*68 + colg + 16*j] = sacc[i][j]*scale;
        __syncthreads();
        // online softmax: 4 threads per row
        {
            int row = tid >> 2, lane = tid & 3;
            float* pr = p_s + row*68 + lane*16;
            float mx = -1e30f;
#pragma unroll
            for (int c = 0; c < 16; c++) mx = fmaxf(mx, pr[c]);
            mx = fmaxf(mx, __shfl_xor_sync(0xffffffffu, mx, 1));
            mx = fmaxf(mx, __shfl_xor_sync(0xffffffffu, mx, 2));
            float mnew = fmaxf(m_s[row], mx);
            float lsum = 0.f;
#pragma unroll
            for (int c = 0; c < 16; c++) {
                float p = __expf(pr[c] - mnew); pr[c] = p; lsum += p;
            }
            lsum += __shfl_xor_sync(0xffffffffu, lsum, 1);
            lsum += __shfl_xor_sync(0xffffffffu, lsum, 2);
            if (lane == 0) {
                float sc = __expf(m_s[row] - mnew);
                sc_s[row] = sc;
                l_s[row]  = l_s[row]*sc + lsum;
                m_s[row]  = mnew;
            }
        }
        __syncthreads();
        // load V tile (overwrites K) + rescale accumulators
        for (int idx = tid*4; idx < 8192; idx += 1024) {
            int r = idx >> 7, d = idx & 127;
            *(float4*)&kv_s[r*132 + d] = *(const float4*)&vb[(size_t)(kt2*64 + r)*DIMM + d];
        }
        float scr[4];
#pragma unroll
        for (int i = 0; i < 4; i++) scr[i] = sc_s[rowg*4 + i];
#pragma unroll
        for (int i = 0; i < 4; i++)
#pragma unroll
            for (int j = 0; j < 8; j++) acc[i][j] *= scr[i];
        __syncthreads();
        // O += P @ V
#pragma unroll 2
        for (int t = 0; t < 64; t++) {
            float p0 = p_s[(rowg*4+0)*68 + t];
            float p1 = p_s[(rowg*4+1)*68 + t];
            float p2 = p_s[(rowg*4+2)*68 + t];
            float p3 = p_s[(rowg*4+3)*68 + t];
            float vv[8];
#pragma unroll
            for (int j = 0; j < 8; j++) vv[j] = kv_s[t*132 + colg + 16*j];
#pragma unroll
            for (int j = 0; j < 8; j++) {
                acc[0][j] += p0*vv[j];
                acc[1][j] += p1*vv[j];
                acc[2][j] += p2*vv[j];
                acc[3][j] += p3*vv[j];
            }
        }
    }
    float invl[4];
#pragma unroll
    for (int i = 0; i < 4; i++) invl[i] = 1.f / l_s[rowg*4 + i];
#pragma unroll
    for (int i = 0; i < 4; i++) {
        int sg = qtile*64 + rowg*4 + i;
#pragma unroll
        for (int j = 0; j < 8; j++)
            y[((size_t)(b*SS + sg))*DIMM + hh*HD + colg + 16*j] = acc[i][j]*invl[i];
    }
}

// ---------------- host ----------------
extern "C" void kernel_launch(void* const* d_in, const int* in_sizes, int n_in,
                              void* d_out, int out_size) {
    const float* x       = (const float*)d_in[0];
    const float* e       = (const float*)d_in[1];
    const float* context = (const float*)d_in[2];
    const float* fcos    = (const float*)d_in[3];
    const float* fsin    = (const float*)d_in[4];
    const float* modu    = (const float*)d_in[5];
    const float* sa_wq = (const float*)d_in[6];  const float* sa_bq = (const float*)d_in[7];
    const float* sa_wk = (const float*)d_in[8];  const float* sa_bk = (const float*)d_in[9];
    const float* sa_wv = (const float*)d_in[10]; const float* sa_bv = (const float*)d_in[11];
    const float* sa_wo = (const float*)d_in[12]; const float* sa_bo = (const float*)d_in[13];
    const float* sa_nq = (const float*)d_in[14]; const float* sa_nk = (const float*)d_in[15];
    const float* ca_wq = (const float*)d_in[16]; const float* ca_bq = (const float*)d_in[17];
    const float* ca_wk = (const float*)d_in[18]; const float* ca_bk = (const float*)d_in[19];
    const float* ca_wv = (const float*)d_in[20]; const float* ca_bv = (const float*)d_in[21];
    const float* ca_wo = (const float*)d_in[22]; const float* ca_bo = (const float*)d_in[23];
    const float* ca_nq = (const float*)d_in[24]; const float* ca_nk = (const float*)d_in[25];
    const float* n3_w  = (const float*)d_in[26]; const float* n3_b  = (const float*)d_in[27];
    const float* w1    = (const float*)d_in[28]; const float* b1    = (const float*)d_in[29];
    const float* w2    = (const float*)d_in[30]; const float* b2    = (const float*)d_in[31];
    float* out = (float*)d_out;

    float *em, *xb, *xn, *tmp, *q, *k, *v, *y, *h, *cb, *sb;
    cudaGetSymbolAddress((void**)&em,  g_em);
    cudaGetSymbolAddress((void**)&cb,  g_cos);
    cudaGetSymbolAddress((void**)&sb,  g_sin);
    cudaGetSymbolAddress((void**)&xb,  g_x);
    cudaGetSymbolAddress((void**)&xn,  g_xn);
    cudaGetSymbolAddress((void**)&tmp, g_tmp);
    cudaGetSymbolAddress((void**)&q,   g_q);
    cudaGetSymbolAddress((void**)&k,   g_k);
    cudaGetSymbolAddress((void**)&v,   g_v);
    cudaGetSymbolAddress((void**)&y,   g_y);
    cudaGetSymbolAddress((void**)&h,   g_h);

    cudaFuncSetAttribute(k_attn, cudaFuncAttributeMaxDynamicSharedMemorySize, ATTN_SMEM);

    dim3 blk(256);
    dim3 gP(DIMM/128, M1/128);       // 4096 x 2048 projections
    dim3 gC(DIMM/128, MC/128);       // 1024 x 2048 ctx projections
    dim3 gF1(FFN/128, M1/128);       // 4096 x 8192
    dim3 gF2(DIMM/128, M1/128);      // 4096 x 2048 (K=8192)
    dim3 gA(SS/64, HEADS, BB);

    // prep
    k_embed<<<(BB*6*DIMM + 255)/256, blk>>>(modu, e, em);
    k_ropetab<<<(SS*64 + 255)/256, blk>>>(fcos, fsin, cb, sb);

    // ---- self attention ----
    k_ln<<<M1, blk>>>(x, em + 1*DIMM, em + 0*DIMM, 1, xn);
    k_gemm<0><<<gP, blk>>>(xn, sa_wq, sa_bq, nullptr, nullptr, tmp, M1, DIMM, DIMM);
    k_rms_t<<<M1, blk>>>(tmp, sa_nq, q, SS, 1);
    k_gemm<0><<<gP, blk>>>(xn, sa_wk, sa_bk, nullptr, nullptr, tmp, M1, DIMM, DIMM);
    k_rms_t<<<M1, blk>>>(tmp, sa_nk, k, SS, 1);
    k_gemm<0><<<gP, blk>>>(xn, sa_wv, sa_bv, nullptr, nullptr, v, M1, DIMM, DIMM);
    k_attn<<<gA, blk, ATTN_SMEM>>>(q, k, v, y, SS);
    k_gemm<3><<<gP, blk>>>(y, sa_wo, sa_bo, x, em + 2*DIMM, xb, M1, DIMM, DIMM);

    // ---- cross attention ----
    k_ln<<<M1, blk>>>(xb, n3_w, n3_b, 0, xn);
    k_gemm<0><<<gP, blk>>>(xn, ca_wq, ca_bq, nullptr, nullptr, tmp, M1, DIMM, DIMM);
    k_rms_t<<<M1, blk>>>(tmp, ca_nq, q, SS, 0);
    k_gemm<0><<<gC, blk>>>(context, ca_wk, ca_bk, nullptr, nullptr, tmp, MC, DIMM, DIMM);
    k_rms_t<<<MC, blk>>>(tmp, ca_nk, k, CTX, 0);
    k_gemm<0><<<gC, blk>>>(context, ca_wv, ca_bv, nullptr, nullptr, v, MC, DIMM, DIMM);
    k_attn<<<gA, blk, ATTN_SMEM>>>(q, k, v, y, CTX);
    k_gemm<2><<<gP, blk>>>(y, ca_wo, ca_bo, xb, nullptr, xb, M1, DIMM, DIMM);

    // ---- FFN ----
    k_ln<<<M1, blk>>>(xb, em + 4*DIMM, em + 3*DIMM, 1, xn);
    k_gemm<1><<<gF1, blk>>>(xn, w1, b1, nullptr, nullptr, h, M1, FFN, DIMM);
    k_gemm<3><<<gF2, blk>>>(h, w2, b2, xb, em + 5*DIMM, out, M1, DIMM, FFN);
}

// round 2
// speedup vs baseline: 2.9719x; 2.9719x over previous
#include <cuda_runtime.h>
#include <cuda_fp16.h>
#include <math.h>
#include <stddef.h>

// ---------------- problem constants ----------------
#define BB     2
#define SS     2048
#define DIMM   2048
#define HEADS  16
#define HD     128
#define FFN    8192
#define CTX    512
#define M1     (BB*SS)        // 4096
#define MC     (BB*CTX)       // 1024
#define EMSTR  (6*DIMM)       // 12288
#define EPSF   1e-6f

// ---------------- device scratch ----------------
__device__ float g_em [BB*6*DIMM];
__device__ float g_cos[SS*(HD/2)];
__device__ float g_sin[SS*(HD/2)];
__device__ float g_x  [M1*DIMM];                 // residual stream (fp32)
__device__ float g_tmp[M1*DIMM];                 // pre-norm q/k/v (fp32)
__device__ float g_q  [BB*HEADS*SS*HD];
__device__ float g_k  [BB*HEADS*SS*HD];
__device__ float g_v  [M1*DIMM];
__device__ __align__(128) __half g_xn [M1*DIMM];     // GEMM A operands (fp16)
__device__ __align__(128) __half g_y  [M1*DIMM];
__device__ __align__(128) __half g_h  [(size_t)M1*FFN];
__device__ __align__(128) __half g_ctx[MC*DIMM];
__device__ __align__(128) __half g_wt [64*1024*1024]; // all W^T fp16

// WT offsets (in elements)
#define WT_Q   ((size_t)0)
#define WT_K   ((size_t)4*1024*1024)
#define WT_V   ((size_t)8*1024*1024)
#define WT_O   ((size_t)12*1024*1024)
#define WT_CQ  ((size_t)16*1024*1024)
#define WT_CK  ((size_t)20*1024*1024)
#define WT_CV  ((size_t)24*1024*1024)
#define WT_CO  ((size_t)28*1024*1024)
#define WT_F1  ((size_t)32*1024*1024)
#define WT_F2  ((size_t)48*1024*1024)

// ---------------- helpers ----------------
__device__ __forceinline__ void cp16(void* smem, const void* g) {
    unsigned s = (unsigned)__cvta_generic_to_shared(smem);
    asm volatile("cp.async.cg.shared.global [%0], [%1], 16;\n" :: "r"(s), "l"(g));
}
__device__ __forceinline__ void cp_commit() { asm volatile("cp.async.commit_group;\n"); }
__device__ __forceinline__ void cp_wait0()  { asm volatile("cp.async.wait_group 0;\n"); }

__device__ __forceinline__ void mma16816(float* d, const unsigned* a, const unsigned* b) {
    asm volatile(
        "mma.sync.aligned.m16n8k16.row.col.f32.f16.f16.f32 "
        "{%0,%1,%2,%3}, {%4,%5,%6,%7}, {%8,%9}, {%0,%1,%2,%3};\n"
        : "+f"(d[0]), "+f"(d[1]), "+f"(d[2]), "+f"(d[3])
        : "r"(a[0]), "r"(a[1]), "r"(a[2]), "r"(a[3]), "r"(b[0]), "r"(b[1]));
}

template<typename OT> __device__ __forceinline__ void stv(OT* p, float v);
template<> __device__ __forceinline__ void stv<float >(float*  p, float v) { *p = v; }
template<> __device__ __forceinline__ void stv<__half>(__half* p, float v) { *p = __float2half(v); }

// ---------------- small kernels ----------------
__global__ void k_embed(const float* __restrict__ mo, const float* __restrict__ e,
                        float* __restrict__ em) {
    int i = blockIdx.x*256 + threadIdx.x;
    if (i < BB*6*DIMM) em[i] = mo[i % EMSTR] + e[i];
}

__global__ void k_ropetab(const float* __restrict__ fc, const float* __restrict__ fs,
                          float* __restrict__ cb, float* __restrict__ sb) {
    int i = blockIdx.x*256 + threadIdx.x;
    if (i >= SS*64) return;
    int s = i >> 6, d = i & 63;
    int f = s >> 8, h = (s >> 4) & 15, w = s & 15;
    int row = (d < 22) ? f : ((d < 43) ? h : w);
    cb[i] = fc[row*64 + d];
    sb[i] = fs[row*64 + d];
}

__global__ void k_tohalf(const float* __restrict__ in, __half* __restrict__ out, int n) {
    int i = blockIdx.x*256 + threadIdx.x;
    if (i < n) out[i] = __float2half(in[i]);
}

// transpose+convert: W[K][N] fp32 -> WT[N][K] fp16
__global__ void k_tr(const float* __restrict__ W, __half* __restrict__ WT, int K, int N) {
    __shared__ float t[32][33];
    int bx = blockIdx.x*32, by = blockIdx.y*32;
    int tx = threadIdx.x, ty = threadIdx.y;    // 32 x 8
#pragma unroll
    for (int i = 0; i < 4; i++)
        t[ty + 8*i][tx] = W[(size_t)(by + ty + 8*i)*N + bx + tx];
    __syncthreads();
#pragma unroll
    for (int i = 0; i < 4; i++)
        WT[(size_t)(bx + ty + 8*i)*K + by + tx] = __float2half(t[tx][ty + 8*i]);
}

// LayerNorm: out(half) = ln(x)*sc + sh
__global__ void k_ln(const float* __restrict__ x, const float* __restrict__ scv,
                     const float* __restrict__ shv, int em_mode, __half* __restrict__ out) {
    __shared__ float buf[DIMM];
    __shared__ float red[256];
    __shared__ float s_m, s_inv;
    int row = blockIdx.x, tid = threadIdx.x;
    const float* xr = x + (size_t)row*DIMM;
    float ls = 0.f;
    for (int c = tid; c < DIMM; c += 256) { float v = xr[c]; buf[c] = v; ls += v; }
    red[tid] = ls; __syncthreads();
    for (int s2 = 128; s2 > 0; s2 >>= 1) { if (tid < s2) red[tid] += red[tid+s2]; __syncthreads(); }
    if (tid == 0) s_m = red[0] * (1.f/DIMM);
    __syncthreads();
    float m = s_m, lv = 0.f;
    for (int c = tid; c < DIMM; c += 256) { float d = buf[c]-m; lv += d*d; }
    red[tid] = lv; __syncthreads();
    for (int s2 = 128; s2 > 0; s2 >>= 1) { if (tid < s2) red[tid] += red[tid+s2]; __syncthreads(); }
    if (tid == 0) s_inv = rsqrtf(red[0]*(1.f/DIMM) + EPSF);
    __syncthreads();
    float inv = s_inv;
    int bo = (row >> 11) * EMSTR;
    __half* orow = out + (size_t)row*DIMM;
    for (int c = tid; c < DIMM; c += 256) {
        float sc, sh;
        if (em_mode) { sc = 1.f + scv[bo+c]; sh = shv[bo+c]; }
        else         { sc = scv[c];          sh = shv[c];    }
        orow[c] = __float2half((buf[c]-m)*inv*sc + sh);
    }
}

// RMS norm + optional RoPE + transpose to [B,H,L,HD] (fp32 out)
__global__ void k_rms_t(const float* __restrict__ in, const float* __restrict__ w,
                        float* __restrict__ outT, int L, int do_rope) {
    __shared__ float buf[DIMM];
    __shared__ float red[256];
    __shared__ float s_inv;
    int row = blockIdx.x, tid = threadIdx.x;
    int b = row / L, s = row % L;
    const float* xr = in + (size_t)row*DIMM;
    float ls = 0.f;
    for (int c = tid; c < DIMM; c += 256) { float v = xr[c]; buf[c] = v; ls += v*v; }
    red[tid] = ls; __syncthreads();
    for (int s2 = 128; s2 > 0; s2 >>= 1) { if (tid < s2) red[tid] += red[tid+s2]; __syncthreads(); }
    if (tid == 0) s_inv = rsqrtf(red[0]*(1.f/DIMM) + EPSF);
    __syncthreads();
    float inv = s_inv;
    if (do_rope) {
        for (int p = tid; p < DIMM/2; p += 256) {
            int hh = p >> 6, i = p & 63;
            float vr = buf[2*p]   * w[2*p]   * inv;
            float vi = buf[2*p+1] * w[2*p+1] * inv;
            float c = g_cos[s*64 + i], sn = g_sin[s*64 + i];
            size_t base = ((size_t)(b*HEADS + hh)*L + s) * HD;
            outT[base + 2*i]   = vr*c - vi*sn;
            outT[base + 2*i+1] = vr*sn + vi*c;
        }
    } else {
        for (int d = tid; d < DIMM; d += 256) {
            int hh = d >> 7, hd = d & 127;
            outT[((size_t)(b*HEADS + hh)*L + s)*HD + hd] = buf[d]*inv*w[d];
        }
    }
}

// ---------------- fp16 tensor-core GEMM ----------------
// C[M,N] = A[M,K](fp16) @ B^T   where Bt is [N][K] fp16.
// EPI 0: +bias  1: gelu(+bias)  2: res+(+bias)  3: res + (+bias)*gate[b,c]
// Tiles: CTA 128x128x32, warp 64x32, mma m16n8k16.
#define LDH 40   // padded halves per smem row (80B = 20 words: conflict-free)
template<int EPI, typename OT>
__global__ __launch_bounds__(256)
void k_gemm_h(const __half* __restrict__ A, const __half* __restrict__ Bt,
              const float* __restrict__ bias, const float* __restrict__ res,
              const float* __restrict__ gate, OT* __restrict__ C,
              int M, int N, int K) {
    __shared__ __align__(16) __half As[2][128*LDH];
    __shared__ __align__(16) __half Bs[2][128*LDH];
    int tid = threadIdx.x;
    int bm = blockIdx.y << 7, bn = blockIdx.x << 7;
    const __half* Ab = A  + (size_t)bm*K;
    const __half* Bb = Bt + (size_t)bn*K;

    int w = tid >> 5, lane = tid & 31;
    int wm = (w >> 2)*64, wn = (w & 3)*32;
    int r = lane >> 2, cc = lane & 3;

    float acc[4][4][4];
#pragma unroll
    for (int i = 0; i < 4; i++)
#pragma unroll
        for (int j = 0; j < 4; j++)
#pragma unroll
            for (int t = 0; t < 4; t++) acc[i][j][t] = 0.f;

    // staging: 512 16B-chunks per operand tile; thread handles chunks tid, tid+256
    auto stage = [&](int st, int kt) {
        int k0 = kt*32;
#pragma unroll
        for (int hh2 = 0; hh2 < 2; hh2++) {
            int ch = tid + hh2*256;
            int mr = ch >> 2, sg = ch & 3;
            cp16(&As[st][mr*LDH + sg*8], Ab + (size_t)mr*K + k0 + sg*8);
            cp16(&Bs[st][mr*LDH + sg*8], Bb + (size_t)mr*K + k0 + sg*8);
        }
        cp_commit();
    };

    stage(0, 0);
    int nk = K >> 5;
    for (int kt = 0; kt < nk; kt++) {
        int st = kt & 1;
        cp_wait0();
        __syncthreads();
        if (kt + 1 < nk) stage(st^1, kt+1);
        const __half* as = As[st];
        const __half* bs = Bs[st];
#pragma unroll
        for (int ks = 0; ks < 2; ks++) {
            unsigned afr[4][4], bfr[4][2];
            int col = ks*16 + 2*cc;
#pragma unroll
            for (int i = 0; i < 4; i++) {
                int row = wm + i*16 + r;
                afr[i][0] = *(const unsigned*)&as[row*LDH + col];
                afr[i][1] = *(const unsigned*)&as[(row+8)*LDH + col];
                afr[i][2] = *(const unsigned*)&as[row*LDH + col + 8];
                afr[i][3] = *(const unsigned*)&as[(row+8)*LDH + col + 8];
            }
#pragma unroll
            for (int j = 0; j < 4; j++) {
                int nrow = wn + j*8 + r;
                bfr[j][0] = *(const unsigned*)&bs[nrow*LDH + col];
                bfr[j][1] = *(const unsigned*)&bs[nrow*LDH + col + 8];
            }
#pragma unroll
            for (int i = 0; i < 4; i++)
#pragma unroll
                for (int j = 0; j < 4; j++)
                    mma16816(acc[i][j], afr[i], bfr[j]);
        }
        __syncthreads();
    }

    // epilogue
#pragma unroll
    for (int i = 0; i < 4; i++) {
        int row0 = bm + wm + i*16 + r;
#pragma unroll
        for (int j = 0; j < 4; j++) {
            int col0 = bn + wn + j*8 + 2*cc;
#pragma unroll
            for (int t = 0; t < 4; t++) {
                int rr = row0 + ((t >> 1) ? 8 : 0);
                int col = col0 + (t & 1);
                float v = acc[i][j][t] + bias[col];
                if (EPI == 1) {
                    float u = v;
                    v = 0.5f*u*(1.f + tanhf(0.7978845608028654f*(u + 0.044715f*u*u*u)));
                }
                if (EPI == 2) v += res[(size_t)rr*N + col];
                if (EPI == 3) v = res[(size_t)rr*N + col] + v * gate[(rr >> 11)*EMSTR + col];
                stv(&C[(size_t)rr*N + col], v);
            }
        }
    }
}

// ---------------- flash attention (fp32, half out) ----------------
#define ATTN_SMEM ((64*132*2 + 64*68 + 192)*4)
__global__ __launch_bounds__(256)
void k_attn(const float* __restrict__ qt, const float* __restrict__ ktp,
            const float* __restrict__ v, __half* __restrict__ y, int Lk) {
    extern __shared__ float smem[];
    float* q_s  = smem;
    float* kv_s = q_s + 64*132;
    float* p_s  = kv_s + 64*132;
    float* m_s  = p_s + 64*68;
    float* l_s  = m_s + 64;
    float* sc_s = l_s + 64;

    int tid = threadIdx.x;
    int qtile = blockIdx.x, hh = blockIdx.y, b = blockIdx.z;
    const float* qb = qt + ((size_t)(b*HEADS + hh)*SS + qtile*64) * HD;
    const float* kb = ktp + (size_t)(b*HEADS + hh)*Lk*HD;
    const float* vb = v + (size_t)b*Lk*DIMM + hh*HD;

    for (int idx = tid*4; idx < 64*128; idx += 1024) {
        int r = idx >> 7, d = idx & 127;
        *(float4*)&q_s[r*132 + d] = *(const float4*)&qb[r*128 + d];
    }
    if (tid < 64) { m_s[tid] = -1e30f; l_s[tid] = 0.f; }

    float acc[4][8];
#pragma unroll
    for (int i = 0; i < 4; i++)
#pragma unroll
        for (int j = 0; j < 8; j++) acc[i][j] = 0.f;

    int rowg = tid >> 4, colg = tid & 15;
    const float scale = 0.08838834764831845f;

    int ntiles = Lk >> 6;
    for (int kt2 = 0; kt2 < ntiles; kt2++) {
        __syncthreads();
        for (int idx = tid*4; idx < 8192; idx += 1024) {
            int r = idx >> 7, d = idx & 127;
            *(float4*)&kv_s[r*132 + d] = *(const float4*)&kb[(size_t)(kt2*64 + r)*128 + d];
        }
        __syncthreads();
        float sacc[4][4];
#pragma unroll
        for (int i = 0; i < 4; i++)
#pragma unroll
            for (int j = 0; j < 4; j++) sacc[i][j] = 0.f;
#pragma unroll 4
        for (int k = 0; k < 128; k++) {
            float a0 = q_s[(rowg*4+0)*132 + k];
            float a1 = q_s[(rowg*4+1)*132 + k];
            float a2 = q_s[(rowg*4+2)*132 + k];
            float a3 = q_s[(rowg*4+3)*132 + k];
            float b0 = kv_s[(colg+ 0)*132 + k];
            float b1 = kv_s[(colg+16)*132 + k];
            float b2 = kv_s[(colg+32)*132 + k];
            float b3 = kv_s[(colg+48)*132 + k];
            sacc[0][0] += a0*b0; sacc[0][1] += a0*b1; sacc[0][2] += a0*b2; sacc[0][3] += a0*b3;
            sacc[1][0] += a1*b0; sacc[1][1] += a1*b1; sacc[1][2] += a1*b2; sacc[1][3] += a1*b3;
            sacc[2][0] += a2*b0; sacc[2][1] += a2*b1; sacc[2][2] += a2*b2; sacc[2][3] += a2*b3;
            sacc[3][0] += a3*b0; sacc[3][1] += a3*b1; sacc[3][2] += a3*b2; sacc[3][3] += a3*b3;
        }
#pragma unroll
        for (int i = 0; i < 4; i++)
#pragma unroll
            for (int j = 0; j < 4; j++)
                p_s[(rowg*4+i)*68 + colg + 16*j] = sacc[i][j]*scale;
        __syncthreads();
        {
            int row = tid >> 2, lane = tid & 3;
            float* pr = p_s + row*68 + lane*16;
            float mx = -1e30f;
#pragma unroll
            for (int c = 0; c < 16; c++) mx = fmaxf(mx, pr[c]);
            mx = fmaxf(mx, __shfl_xor_sync(0xffffffffu, mx, 1));
            mx = fmaxf(mx, __shfl_xor_sync(0xffffffffu, mx, 2));
            float mnew = fmaxf(m_s[row], mx);
            float lsum = 0.f;
#pragma unroll
            for (int c = 0; c < 16; c++) {
                float p = __expf(pr[c] - mnew); pr[c] = p; lsum += p;
            }
            lsum += __shfl_xor_sync(0xffffffffu, lsum, 1);
            lsum += __shfl_xor_sync(0xffffffffu, lsum, 2);
            if (lane == 0) {
                float sc = __expf(m_s[row] - mnew);
                sc_s[row] = sc;
                l_s[row]  = l_s[row]*sc + lsum;
                m_s[row]  = mnew;
            }
        }
        __syncthreads();
        for (int idx = tid*4; idx < 8192; idx += 1024) {
            int r = idx >> 7, d = idx & 127;
            *(float4*)&kv_s[r*132 + d] = *(const float4*)&vb[(size_t)(kt2*64 + r)*DIMM + d];
        }
        float scr[4];
#pragma unroll
        for (int i = 0; i < 4; i++) scr[i] = sc_s[rowg*4 + i];
#pragma unroll
        for (int i = 0; i < 4; i++)
#pragma unroll
            for (int j = 0; j < 8; j++) acc[i][j] *= scr[i];
        __syncthreads();
#pragma unroll 2
        for (int t = 0; t < 64; t++) {
            float p0 = p_s[(rowg*4+0)*68 + t];
            float p1 = p_s[(rowg*4+1)*68 + t];
            float p2 = p_s[(rowg*4+2)*68 + t];
            float p3 = p_s[(rowg*4+3)*68 + t];
            float vv[8];
#pragma unroll
            for (int j = 0; j < 8; j++) vv[j] = kv_s[t*132 + colg + 16*j];
#pragma unroll
            for (int j = 0; j < 8; j++) {
                acc[0][j] += p0*vv[j];
                acc[1][j] += p1*vv[j];
                acc[2][j] += p2*vv[j];
                acc[3][j] += p3*vv[j];
            }
        }
    }
    float invl[4];
#pragma unroll
    for (int i = 0; i < 4; i++) invl[i] = 1.f / l_s[rowg*4 + i];
#pragma unroll
    for (int i = 0; i < 4; i++) {
        int sg = qtile*64 + rowg*4 + i;
#pragma unroll
        for (int j = 0; j < 8; j++)
            y[((size_t)(b*SS + sg))*DIMM + hh*HD + colg + 16*j] = __float2half(acc[i][j]*invl[i]);
    }
}

// ---------------- host ----------------
extern "C" void kernel_launch(void* const* d_in, const int* in_sizes, int n_in,
                              void* d_out, int out_size) {
    const float* x       = (const float*)d_in[0];
    const float* e       = (const float*)d_in[1];
    const float* context = (const float*)d_in[2];
    const float* fcos    = (const float*)d_in[3];
    const float* fsin    = (const float*)d_in[4];
    const float* modu    = (const float*)d_in[5];
    const float* sa_wq = (const float*)d_in[6];  const float* sa_bq = (const float*)d_in[7];
    const float* sa_wk = (const float*)d_in[8];  const float* sa_bk = (const float*)d_in[9];
    const float* sa_wv = (const float*)d_in[10]; const float* sa_bv = (const float*)d_in[11];
    const float* sa_wo = (const float*)d_in[12]; const float* sa_bo = (const float*)d_in[13];
    const float* sa_nq = (const float*)d_in[14]; const float* sa_nk = (const float*)d_in[15];
    const float* ca_wq = (const float*)d_in[16]; const float* ca_bq = (const float*)d_in[17];
    const float* ca_wk = (const float*)d_in[18]; const float* ca_bk = (const float*)d_in[19];
    const float* ca_wv = (const float*)d_in[20]; const float* ca_bv = (const float*)d_in[21];
    const float* ca_wo = (const float*)d_in[22]; const float* ca_bo = (const float*)d_in[23];
    const float* ca_nq = (const float*)d_in[24]; const float* ca_nk = (const float*)d_in[25];
    const float* n3_w  = (const float*)d_in[26]; const float* n3_b  = (const float*)d_in[27];
    const float* w1    = (const float*)d_in[28]; const float* b1    = (const float*)d_in[29];
    const float* w2    = (const float*)d_in[30]; const float* b2    = (const float*)d_in[31];
    float* out = (float*)d_out;

    float *em, *cb, *sb, *xb, *tmp, *q, *k, *v;
    __half *xn, *y, *h, *ctxh, *wt;
    cudaGetSymbolAddress((void**)&em,   g_em);
    cudaGetSymbolAddress((void**)&cb,   g_cos);
    cudaGetSymbolAddress((void**)&sb,   g_sin);
    cudaGetSymbolAddress((void**)&xb,   g_x);
    cudaGetSymbolAddress((void**)&tmp,  g_tmp);
    cudaGetSymbolAddress((void**)&q,    g_q);
    cudaGetSymbolAddress((void**)&k,    g_k);
    cudaGetSymbolAddress((void**)&v,    g_v);
    cudaGetSymbolAddress((void**)&xn,   g_xn);
    cudaGetSymbolAddress((void**)&y,    g_y);
    cudaGetSymbolAddress((void**)&h,    g_h);
    cudaGetSymbolAddress((void**)&ctxh, g_ctx);
    cudaGetSymbolAddress((void**)&wt,   g_wt);

    cudaFuncSetAttribute(k_attn, cudaFuncAttributeMaxDynamicSharedMemorySize, ATTN_SMEM);

    dim3 blk(256);
    dim3 trb(32, 8);
    dim3 trD(DIMM/32, DIMM/32);      // 2048x2048
    dim3 trF1(FFN/32, DIMM/32);      // W1: K=2048, N=8192
    dim3 trF2(DIMM/32, FFN/32);      // W2: K=8192, N=2048
    dim3 gP(DIMM/128, M1/128);
    dim3 gC(DIMM/128, MC/128);
    dim3 gF1(FFN/128, M1/128);
    dim3 gF2(DIMM/128, M1/128);
    dim3 gA(SS/64, HEADS, BB);

    // ---- pre-pass: weight transpose/convert + context convert ----
    k_tr<<<trD,  trb>>>(sa_wq, wt + WT_Q,  DIMM, DIMM);
    k_tr<<<trD,  trb>>>(sa_wk, wt + WT_K,  DIMM, DIMM);
    k_tr<<<trD,  trb>>>(sa_wv, wt + WT_V,  DIMM, DIMM);
    k_tr<<<trD,  trb>>>(sa_wo, wt + WT_O,  DIMM, DIMM);
    k_tr<<<trD,  trb>>>(ca_wq, wt + WT_CQ, DIMM, DIMM);
    k_tr<<<trD,  trb>>>(ca_wk, wt + WT_CK, DIMM, DIMM);
    k_tr<<<trD,  trb>>>(ca_wv, wt + WT_CV, DIMM, DIMM);
    k_tr<<<trD,  trb>>>(ca_wo, wt + WT_CO, DIMM, DIMM);
    k_tr<<<trF1, trb>>>(w1,    wt + WT_F1, DIMM, FFN);
    k_tr<<<trF2, trb>>>(w2,    wt + WT_F2, FFN,  DIMM);
    k_tohalf<<<(MC*DIMM + 255)/256, blk>>>(context, ctxh, MC*DIMM);
    k_embed<<<(BB*6*DIMM + 255)/256, blk>>>(modu, e, em);
    k_ropetab<<<(SS*64 + 255)/256, blk>>>(fcos, fsin, cb, sb);

    // ---- self attention ----
    k_ln<<<M1, blk>>>(x, em + 1*DIMM, em + 0*DIMM, 1, xn);
    k_gemm_h<0,float><<<gP, blk>>>(xn, wt + WT_Q, sa_bq, nullptr, nullptr, tmp, M1, DIMM, DIMM);
    k_rms_t<<<M1, blk>>>(tmp, sa_nq, q, SS, 1);
    k_gemm_h<0,float><<<gP, blk>>>(xn, wt + WT_K, sa_bk, nullptr, nullptr, tmp, M1, DIMM, DIMM);
    k_rms_t<<<M1, blk>>>(tmp, sa_nk, k, SS, 1);
    k_gemm_h<0,float><<<gP, blk>>>(xn, wt + WT_V, sa_bv, nullptr, nullptr, v, M1, DIMM, DIMM);
    k_attn<<<gA, blk, ATTN_SMEM>>>(q, k, v, y, SS);
    k_gemm_h<3,float><<<gP, blk>>>(y, wt + WT_O, sa_bo, x, em + 2*DIMM, xb, M1, DIMM, DIMM);

    // ---- cross attention ----
    k_ln<<<M1, blk>>>(xb, n3_w, n3_b, 0, xn);
    k_gemm_h<0,float><<<gP, blk>>>(xn, wt + WT_CQ, ca_bq, nullptr, nullptr, tmp, M1, DIMM, DIMM);
    k_rms_t<<<M1, blk>>>(tmp, ca_nq, q, SS, 0);
    k_gemm_h<0,float><<<gC, blk>>>(ctxh, wt + WT_CK, ca_bk, nullptr, nullptr, tmp, MC, DIMM, DIMM);
    k_rms_t<<<MC, blk>>>(tmp, ca_nk, k, CTX, 0);
    k_gemm_h<0,float><<<gC, blk>>>(ctxh, wt + WT_CV, ca_bv, nullptr, nullptr, v, MC, DIMM, DIMM);
    k_attn<<<gA, blk, ATTN_SMEM>>>(q, k, v, y, CTX);
    k_gemm_h<2,float><<<gP, blk>>>(y, wt + WT_CO, ca_bo, xb, nullptr, xb, M1, DIMM, DIMM);

    // ---- FFN ----
    k_ln<<<M1, blk>>>(xb, em + 4*DIMM, em + 3*DIMM, 1, xn);
    k_gemm_h<1,__half><<<gF1, blk>>>(xn, wt + WT_F1, b1, nullptr, nullptr, h, M1, FFN, DIMM);
    k_gemm_h<3,float><<<gF2, blk>>>(h, wt + WT_F2, b2, xb, em + 5*DIMM, out, M1, DIMM, FFN);
}

// round 5
// speedup vs baseline: 5.3569x; 1.8025x over previous
#include <cuda_runtime.h>
#include <cuda_fp16.h>
#include <math.h>
#include <stddef.h>

// ---------------- problem constants ----------------
#define BB     2
#define SS     2048
#define DIMM   2048
#define HEADS  16
#define HD     128
#define FFN    8192
#define CTX    512
#define M1     (BB*SS)
#define MC     (BB*CTX)
#define EMSTR  (6*DIMM)
#define EPSF   1e-6f

// ---------------- device scratch ----------------
__device__ float g_em [BB*6*DIMM];
__device__ float g_cos[SS*(HD/2)];
__device__ float g_sin[SS*(HD/2)];
__device__ float g_x  [M1*DIMM];                 // residual stream (fp32)
__device__ float g_tmp[M1*DIMM];                 // pre-norm q/k (fp32)
__device__ __align__(128) __half g_qh [BB*HEADS*SS*HD];
__device__ __align__(128) __half g_kh [BB*HEADS*SS*HD];
__device__ __align__(128) __half g_vh [M1*DIMM];
__device__ __align__(128) __half g_xn [M1*DIMM];
__device__ __align__(128) __half g_y  [M1*DIMM];
__device__ __align__(128) __half g_h  [(size_t)M1*FFN];
__device__ __align__(128) __half g_ctx[MC*DIMM];
__device__ __align__(128) __half g_wt [64*1024*1024];

#define WT_Q   ((size_t)0)
#define WT_K   ((size_t)4*1024*1024)
#define WT_V   ((size_t)8*1024*1024)
#define WT_O   ((size_t)12*1024*1024)
#define WT_CQ  ((size_t)16*1024*1024)
#define WT_CK  ((size_t)20*1024*1024)
#define WT_CV  ((size_t)24*1024*1024)
#define WT_CO  ((size_t)28*1024*1024)
#define WT_F1  ((size_t)32*1024*1024)
#define WT_F2  ((size_t)48*1024*1024)

// ---------------- helpers ----------------
__device__ __forceinline__ void cp16(void* smem, const void* g) {
    unsigned s = (unsigned)__cvta_generic_to_shared(smem);
    asm volatile("cp.async.cg.shared.global [%0], [%1], 16;\n" :: "r"(s), "l"(g));
}
__device__ __forceinline__ void cp_commit() { asm volatile("cp.async.commit_group;\n"); }
__device__ __forceinline__ void cp_wait0()  { asm volatile("cp.async.wait_group 0;\n"); }
__device__ __forceinline__ void cp_wait1()  { asm volatile("cp.async.wait_group 1;\n"); }

__device__ __forceinline__ void mma16816(float* d, const unsigned* a, const unsigned* b) {
    asm volatile(
        "mma.sync.aligned.m16n8k16.row.col.f32.f16.f16.f32 "
        "{%0,%1,%2,%3}, {%4,%5,%6,%7}, {%8,%9}, {%0,%1,%2,%3};\n"
        : "+f"(d[0]), "+f"(d[1]), "+f"(d[2]), "+f"(d[3])
        : "r"(a[0]), "r"(a[1]), "r"(a[2]), "r"(a[3]), "r"(b[0]), "r"(b[1]));
}
__device__ __forceinline__ void ldsm4t(unsigned& r0, unsigned& r1, unsigned& r2, unsigned& r3,
                                       unsigned saddr) {
    asm volatile("ldmatrix.sync.aligned.m8n8.x4.trans.shared.b16 {%0,%1,%2,%3}, [%4];\n"
                 : "=r"(r0), "=r"(r1), "=r"(r2), "=r"(r3) : "r"(saddr));
}
__device__ __forceinline__ unsigned packh2(float a, float b) {
    __half2 h = __floats2half2_rn(a, b);
    return *reinterpret_cast<unsigned*>(&h);
}

template<typename OT> __device__ __forceinline__ void stv(OT* p, float v);
template<> __device__ __forceinline__ void stv<float >(float*  p, float v) { *p = v; }
template<> __device__ __forceinline__ void stv<__half>(__half* p, float v) { *p = __float2half(v); }

// ---------------- small kernels ----------------
__global__ void k_embed(const float* __restrict__ mo, const float* __restrict__ e,
                        float* __restrict__ em) {
    int i = blockIdx.x*256 + threadIdx.x;
    if (i < BB*6*DIMM) em[i] = mo[i % EMSTR] + e[i];
}

__global__ void k_ropetab(const float* __restrict__ fc, const float* __restrict__ fs,
                          float* __restrict__ cb, float* __restrict__ sb) {
    int i = blockIdx.x*256 + threadIdx.x;
    if (i >= SS*64) return;
    int s = i >> 6, d = i & 63;
    int f = s >> 8, h = (s >> 4) & 15, w = s & 15;
    int row = (d < 22) ? f : ((d < 43) ? h : w);
    cb[i] = fc[row*64 + d];
    sb[i] = fs[row*64 + d];
}

__global__ void k_tohalf(const float* __restrict__ in, __half* __restrict__ out, int n) {
    int i = blockIdx.x*256 + threadIdx.x;
    if (i < n) out[i] = __float2half(in[i]);
}

__global__ void k_tr(const float* __restrict__ W, __half* __restrict__ WT, int K, int N) {
    __shared__ float t[32][33];
    int bx = blockIdx.x*32, by = blockIdx.y*32;
    int tx = threadIdx.x, ty = threadIdx.y;
#pragma unroll
    for (int i = 0; i < 4; i++)
        t[ty + 8*i][tx] = W[(size_t)(by + ty + 8*i)*N + bx + tx];
    __syncthreads();
#pragma unroll
    for (int i = 0; i < 4; i++)
        WT[(size_t)(bx + ty + 8*i)*K + by + tx] = __float2half(t[tx][ty + 8*i]);
}

__global__ void k_ln(const float* __restrict__ x, const float* __restrict__ scv,
                     const float* __restrict__ shv, int em_mode, __half* __restrict__ out) {
    __shared__ float buf[DIMM];
    __shared__ float red[256];
    __shared__ float s_m, s_inv;
    int row = blockIdx.x, tid = threadIdx.x;
    const float* xr = x + (size_t)row*DIMM;
    float ls = 0.f;
    for (int c = tid; c < DIMM; c += 256) { float v = xr[c]; buf[c] = v; ls += v; }
    red[tid] = ls; __syncthreads();
    for (int s2 = 128; s2 > 0; s2 >>= 1) { if (tid < s2) red[tid] += red[tid+s2]; __syncthreads(); }
    if (tid == 0) s_m = red[0] * (1.f/DIMM);
    __syncthreads();
    float m = s_m, lv = 0.f;
    for (int c = tid; c < DIMM; c += 256) { float d = buf[c]-m; lv += d*d; }
    red[tid] = lv; __syncthreads();
    for (int s2 = 128; s2 > 0; s2 >>= 1) { if (tid < s2) red[tid] += red[tid+s2]; __syncthreads(); }
    if (tid == 0) s_inv = rsqrtf(red[0]*(1.f/DIMM) + EPSF);
    __syncthreads();
    float inv = s_inv;
    int bo = (row >> 11) * EMSTR;
    __half* orow = out + (size_t)row*DIMM;
    for (int c = tid; c < DIMM; c += 256) {
        float sc, sh;
        if (em_mode) { sc = 1.f + scv[bo+c]; sh = shv[bo+c]; }
        else         { sc = scv[c];          sh = shv[c];    }
        orow[c] = __float2half((buf[c]-m)*inv*sc + sh);
    }
}

// RMS norm + optional RoPE + transpose to [B,H,L,HD], fp16 out, with output scale
__global__ void k_rms_t(const float* __restrict__ in, const float* __restrict__ w,
                        __half* __restrict__ outT, int L, int do_rope, float oscale) {
    __shared__ float buf[DIMM];
    __shared__ float red[256];
    __shared__ float s_inv;
    int row = blockIdx.x, tid = threadIdx.x;
    int b = row / L, s = row % L;
    const float* xr = in + (size_t)row*DIMM;
    float ls = 0.f;
    for (int c = tid; c < DIMM; c += 256) { float v = xr[c]; buf[c] = v; ls += v*v; }
    red[tid] = ls; __syncthreads();
    for (int s2 = 128; s2 > 0; s2 >>= 1) { if (tid < s2) red[tid] += red[tid+s2]; __syncthreads(); }
    if (tid == 0) s_inv = rsqrtf(red[0]*(1.f/DIMM) + EPSF);
    __syncthreads();
    float inv = s_inv * oscale;
    if (do_rope) {
        for (int p = tid; p < DIMM/2; p += 256) {
            int hh = p >> 6, i = p & 63;
            float vr = buf[2*p]   * w[2*p]   * inv;
            float vi = buf[2*p+1] * w[2*p+1] * inv;
            float c = g_cos[s*64 + i], sn = g_sin[s*64 + i];
            size_t base = ((size_t)(b*HEADS + hh)*L + s) * HD;
            outT[base + 2*i]   = __float2half(vr*c - vi*sn);
            outT[base + 2*i+1] = __float2half(vr*sn + vi*c);
        }
    } else {
        for (int d = tid; d < DIMM; d += 256) {
            int hh = d >> 7, hd = d & 127;
            outT[((size_t)(b*HEADS + hh)*L + s)*HD + hd] = __float2half(buf[d]*inv*w[d]);
        }
    }
}

// ---------------- fp16 tensor-core GEMM ----------------
#define LDH 40
template<int EPI, typename OT>
__global__ __launch_bounds__(256)
void k_gemm_h(const __half* __restrict__ A, const __half* __restrict__ Bt,
              const float* __restrict__ bias, const float* __restrict__ res,
              const float* __restrict__ gate, OT* __restrict__ C,
              int M, int N, int K) {
    __shared__ __align__(16) __half As[2][128*LDH];
    __shared__ __align__(16) __half Bs[2][128*LDH];
    int tid = threadIdx.x;
    int bm = blockIdx.y << 7, bn = blockIdx.x << 7;
    const __half* Ab = A  + (size_t)bm*K;
    const __half* Bb = Bt + (size_t)bn*K;

    int w = tid >> 5, lane = tid & 31;
    int wm = (w >> 2)*64, wn = (w & 3)*32;
    int r = lane >> 2, cc = lane & 3;

    float acc[4][4][4];
#pragma unroll
    for (int i = 0; i < 4; i++)
#pragma unroll
        for (int j = 0; j < 4; j++)
#pragma unroll
            for (int t = 0; t < 4; t++) acc[i][j][t] = 0.f;

    auto stage = [&](int st, int kt) {
        int k0 = kt*32;
#pragma unroll
        for (int hh2 = 0; hh2 < 2; hh2++) {
            int ch = tid + hh2*256;
            int mr = ch >> 2, sg = ch & 3;
            cp16(&As[st][mr*LDH + sg*8], Ab + (size_t)mr*K + k0 + sg*8);
            cp16(&Bs[st][mr*LDH + sg*8], Bb + (size_t)mr*K + k0 + sg*8);
        }
        cp_commit();
    };

    stage(0, 0);
    int nk = K >> 5;
    for (int kt = 0; kt < nk; kt++) {
        int st = kt & 1;
        cp_wait0();
        __syncthreads();
        if (kt + 1 < nk) stage(st^1, kt+1);
        const __half* as = As[st];
        const __half* bs = Bs[st];
#pragma unroll
        for (int ks = 0; ks < 2; ks++) {
            unsigned afr[4][4], bfr[4][2];
            int col = ks*16 + 2*cc;
#pragma unroll
            for (int i = 0; i < 4; i++) {
                int row = wm + i*16 + r;
                afr[i][0] = *(const unsigned*)&as[row*LDH + col];
                afr[i][1] = *(const unsigned*)&as[(row+8)*LDH + col];
                afr[i][2] = *(const unsigned*)&as[row*LDH + col + 8];
                afr[i][3] = *(const unsigned*)&as[(row+8)*LDH + col + 8];
            }
#pragma unroll
            for (int j = 0; j < 4; j++) {
                int nrow = wn + j*8 + r;
                bfr[j][0] = *(const unsigned*)&bs[nrow*LDH + col];
                bfr[j][1] = *(const unsigned*)&bs[nrow*LDH + col + 8];
            }
#pragma unroll
            for (int i = 0; i < 4; i++)
#pragma unroll
                for (int j = 0; j < 4; j++)
                    mma16816(acc[i][j], afr[i], bfr[j]);
        }
        __syncthreads();
    }

#pragma unroll
    for (int i = 0; i < 4; i++) {
        int row0 = bm + wm + i*16 + r;
#pragma unroll
        for (int j = 0; j < 4; j++) {
            int col0 = bn + wn + j*8 + 2*cc;
#pragma unroll
            for (int t = 0; t < 4; t++) {
                int rr = row0 + ((t >> 1) ? 8 : 0);
                int col = col0 + (t & 1);
                float v = acc[i][j][t] + bias[col];
                if (EPI == 1) {
                    float u = v;
                    v = 0.5f*u*(1.f + tanhf(0.7978845608028654f*(u + 0.044715f*u*u*u)));
                }
                if (EPI == 2) v += res[(size_t)rr*N + col];
                if (EPI == 3) v = res[(size_t)rr*N + col] + v * gate[(rr >> 11)*EMSTR + col];
                stv(&C[(size_t)rr*N + col], v);
            }
        }
    }
}

// ---------------- fp16 flash attention ----------------
// q,k: [B,H,L,HD] fp16 (q pre-scaled by 1/sqrt(HD)); v: [B,Lk,DIM] fp16; y: [B,S,DIM] fp16
#define AT_LDS 136
#define KVSZ   (64*AT_LDS)
#define ATTN_H_SMEM (4*KVSZ*2)   // bytes
__global__ __launch_bounds__(128)
void k_attn_h(const __half* __restrict__ qt, const __half* __restrict__ kt,
              const __half* __restrict__ vh, __half* __restrict__ y, int Lk) {
    extern __shared__ __half smh[];
    __half* Kb = smh;               // 2 * KVSZ
    __half* Vb = smh + 2*KVSZ;      // 2 * KVSZ

    int tid = threadIdx.x;
    int w = tid >> 5, lane = tid & 31;
    int r = lane >> 2, cc = lane & 3;
    int qtile = blockIdx.x, hh = blockIdx.y, b = blockIdx.z;

    const __half* qb = qt + ((size_t)(b*HEADS + hh)*SS + qtile*64) * HD;
    const __half* kb = kt + (size_t)(b*HEADS + hh)*Lk*HD;
    const __half* vb = vh + (size_t)b*Lk*DIMM + hh*HD;

    // stage K+V tile: 64 rows x 128 halves = 1024 16B-chunks per operand
    auto stage_kv = [&](int st, int t2) {
        __half* Kd = Kb + st*KVSZ;
        __half* Vd = Vb + st*KVSZ;
#pragma unroll
        for (int i2 = 0; i2 < 8; i2++) {
            int ch = tid + i2*128;           // 0..1023
            int row = ch >> 4, sg = ch & 15;
            cp16(&Kd[row*AT_LDS + sg*8], kb + (size_t)(t2*64 + row)*HD + sg*8);
            cp16(&Vd[row*AT_LDS + sg*8], vb + (size_t)(t2*64 + row)*DIMM + sg*8);
        }
        cp_commit();
    };

    // initial: Q tile -> Kb buf1, KV tile0 -> buf0
    {
        __half* Qd = Kb + KVSZ;
#pragma unroll
        for (int i2 = 0; i2 < 8; i2++) {
            int ch = tid + i2*128;
            int row = ch >> 4, sg = ch & 15;
            cp16(&Qd[row*AT_LDS + sg*8], qb + (size_t)row*HD + sg*8);
        }
        stage_kv(0, 0);
    }
    cp_wait0();
    __syncthreads();

    // Q fragments (registers, reused for all KV tiles)
    unsigned afrq[8][4];
    {
        const __half* Qs = Kb + KVSZ;
#pragma unroll
        for (int kc = 0; kc < 8; kc++) {
            int row = w*16 + r, col = kc*16 + 2*cc;
            afrq[kc][0] = *(const unsigned*)&Qs[row*AT_LDS + col];
            afrq[kc][1] = *(const unsigned*)&Qs[(row+8)*AT_LDS + col];
            afrq[kc][2] = *(const unsigned*)&Qs[row*AT_LDS + col + 8];
            afrq[kc][3] = *(const unsigned*)&Qs[(row+8)*AT_LDS + col + 8];
        }
    }

    float acc[16][4];
#pragma unroll
    for (int i = 0; i < 16; i++)
#pragma unroll
        for (int t = 0; t < 4; t++) acc[i][t] = 0.f;
    float m0 = -1e30f, m1 = -1e30f, l0 = 0.f, l1 = 0.f;

    int ntiles = Lk >> 6;
    for (int t2 = 0; t2 < ntiles; t2++) {
        __syncthreads();
        if (t2 + 1 < ntiles) { stage_kv((t2+1) & 1, t2+1); cp_wait1(); }
        else                 { cp_wait0(); }
        __syncthreads();
        const __half* Ks = Kb + (t2&1)*KVSZ;
        const __half* Vs = Vb + (t2&1)*KVSZ;

        // ---- S = Q K^T (16x64 per warp) ----
        float sacc[8][4];
#pragma unroll
        for (int nb = 0; nb < 8; nb++)
#pragma unroll
            for (int t = 0; t < 4; t++) sacc[nb][t] = 0.f;
#pragma unroll
        for (int kc = 0; kc < 8; kc++) {
            unsigned bfr[8][2];
            int col = kc*16 + 2*cc;
#pragma unroll
            for (int nb = 0; nb < 8; nb++) {
                int krow = nb*8 + r;
                bfr[nb][0] = *(const unsigned*)&Ks[krow*AT_LDS + col];
                bfr[nb][1] = *(const unsigned*)&Ks[krow*AT_LDS + col + 8];
            }
#pragma unroll
            for (int nb = 0; nb < 8; nb++) mma16816(sacc[nb], afrq[kc], bfr[nb]);
        }

        // ---- online softmax ----
        float mx0 = -1e30f, mx1 = -1e30f;
#pragma unroll
        for (int nb = 0; nb < 8; nb++) {
            mx0 = fmaxf(mx0, fmaxf(sacc[nb][0], sacc[nb][1]));
            mx1 = fmaxf(mx1, fmaxf(sacc[nb][2], sacc[nb][3]));
        }
        mx0 = fmaxf(mx0, __shfl_xor_sync(0xffffffffu, mx0, 1));
        mx0 = fmaxf(mx0, __shfl_xor_sync(0xffffffffu, mx0, 2));
        mx1 = fmaxf(mx1, __shfl_xor_sync(0xffffffffu, mx1, 1));
        mx1 = fmaxf(mx1, __shfl_xor_sync(0xffffffffu, mx1, 2));
        float mn0 = fmaxf(m0, mx0), mn1 = fmaxf(m1, mx1);
        float esc0 = __expf(m0 - mn0), esc1 = __expf(m1 - mn1);
        m0 = mn0; m1 = mn1;
        float ls0 = 0.f, ls1 = 0.f;
#pragma unroll
        for (int nb = 0; nb < 8; nb++) {
            sacc[nb][0] = __expf(sacc[nb][0] - mn0); ls0 += sacc[nb][0];
            sacc[nb][1] = __expf(sacc[nb][1] - mn0); ls0 += sacc[nb][1];
            sacc[nb][2] = __expf(sacc[nb][2] - mn1); ls1 += sacc[nb][2];
            sacc[nb][3] = __expf(sacc[nb][3] - mn1); ls1 += sacc[nb][3];
        }
        ls0 += __shfl_xor_sync(0xffffffffu, ls0, 1);
        ls0 += __shfl_xor_sync(0xffffffffu, ls0, 2);
        ls1 += __shfl_xor_sync(0xffffffffu, ls1, 1);
        ls1 += __shfl_xor_sync(0xffffffffu, ls1, 2);
        l0 = l0*esc0 + ls0;
        l1 = l1*esc1 + ls1;

        unsigned pf[4][4];
#pragma unroll
        for (int kc = 0; kc < 4; kc++) {
            pf[kc][0] = packh2(sacc[2*kc][0],   sacc[2*kc][1]);
            pf[kc][1] = packh2(sacc[2*kc][2],   sacc[2*kc][3]);
            pf[kc][2] = packh2(sacc[2*kc+1][0], sacc[2*kc+1][1]);
            pf[kc][3] = packh2(sacc[2*kc+1][2], sacc[2*kc+1][3]);
        }
#pragma unroll
        for (int nb = 0; nb < 16; nb++) {
            acc[nb][0] *= esc0; acc[nb][1] *= esc0;
            acc[nb][2] *= esc1; acc[nb][3] *= esc1;
        }

        // ---- O += P V ----
        unsigned vbase = (unsigned)__cvta_generic_to_shared(Vs);
        int lrow = (lane & 7) + ((lane >> 3) & 1)*8;
        int lcol = (lane >> 4)*8;
#pragma unroll
        for (int np = 0; np < 8; np++) {
#pragma unroll
            for (int kc = 0; kc < 4; kc++) {
                unsigned r0, r1, r2, r3;
                unsigned addr = vbase + (unsigned)(((kc*16 + lrow)*AT_LDS + np*16 + lcol)*2);
                ldsm4t(r0, r1, r2, r3, addr);
                unsigned b0[2] = {r0, r1};
                unsigned b1[2] = {r2, r3};
                mma16816(acc[np*2],     pf[kc], b0);
                mma16816(acc[np*2 + 1], pf[kc], b1);
            }
        }
    }

    // ---- epilogue ----
    float inv0 = 1.f/l0, inv1 = 1.f/l1;
    int row0 = qtile*64 + w*16 + r;
    __half* yb = y + (size_t)b*SS*DIMM + hh*HD;
#pragma unroll
    for (int nb = 0; nb < 16; nb++) {
        int col = nb*8 + 2*cc;
        __half2 h0 = __floats2half2_rn(acc[nb][0]*inv0, acc[nb][1]*inv0);
        __half2 h1 = __floats2half2_rn(acc[nb][2]*inv1, acc[nb][3]*inv1);
        *(__half2*)&yb[(size_t)row0*DIMM + col]     = h0;
        *(__half2*)&yb[(size_t)(row0+8)*DIMM + col] = h1;
    }
}

// ---------------- host ----------------
extern "C" void kernel_launch(void* const* d_in, const int* in_sizes, int n_in,
                              void* d_out, int out_size) {
    const float* x       = (const float*)d_in[0];
    const float* e       = (const float*)d_in[1];
    const float* context = (const float*)d_in[2];
    const float* fcos    = (const float*)d_in[3];
    const float* fsin    = (const float*)d_in[4];
    const float* modu    = (const float*)d_in[5];
    const float* sa_wq = (const float*)d_in[6];  const float* sa_bq = (const float*)d_in[7];
    const float* sa_wk = (const float*)d_in[8];  const float* sa_bk = (const float*)d_in[9];
    const float* sa_wv = (const float*)d_in[10]; const float* sa_bv = (const float*)d_in[11];
    const float* sa_wo = (const float*)d_in[12]; const float* sa_bo = (const float*)d_in[13];
    const float* sa_nq = (const float*)d_in[14]; const float* sa_nk = (const float*)d_in[15];
    const float* ca_wq = (const float*)d_in[16]; const float* ca_bq = (const float*)d_in[17];
    const float* ca_wk = (const float*)d_in[18]; const float* ca_bk = (const float*)d_in[19];
    const float* ca_wv = (const float*)d_in[20]; const float* ca_bv = (const float*)d_in[21];
    const float* ca_wo = (const float*)d_in[22]; const float* ca_bo = (const float*)d_in[23];
    const float* ca_nq = (const float*)d_in[24]; const float* ca_nk = (const float*)d_in[25];
    const float* n3_w  = (const float*)d_in[26]; const float* n3_b  = (const float*)d_in[27];
    const float* w1    = (const float*)d_in[28]; const float* b1    = (const float*)d_in[29];
    const float* w2    = (const float*)d_in[30]; const float* b2    = (const float*)d_in[31];
    float* out = (float*)d_out;

    float *em, *cb, *sb, *xb, *tmp;
    __half *qh, *kh, *vhp, *xn, *y, *h, *ctxh, *wt;
    cudaGetSymbolAddress((void**)&em,   g_em);
    cudaGetSymbolAddress((void**)&cb,   g_cos);
    cudaGetSymbolAddress((void**)&sb,   g_sin);
    cudaGetSymbolAddress((void**)&xb,   g_x);
    cudaGetSymbolAddress((void**)&tmp,  g_tmp);
    cudaGetSymbolAddress((void**)&qh,   g_qh);
    cudaGetSymbolAddress((void**)&kh,   g_kh);
    cudaGetSymbolAddress((void**)&vhp,  g_vh);
    cudaGetSymbolAddress((void**)&xn,   g_xn);
    cudaGetSymbolAddress((void**)&y,    g_y);
    cudaGetSymbolAddress((void**)&h,    g_h);
    cudaGetSymbolAddress((void**)&ctxh, g_ctx);
    cudaGetSymbolAddress((void**)&wt,   g_wt);

    cudaFuncSetAttribute(k_attn_h, cudaFuncAttributeMaxDynamicSharedMemorySize, ATTN_H_SMEM);

    const float QSC = 0.08838834764831845f;  // 1/sqrt(128)

    dim3 blk(256);
    dim3 trb(32, 8);
    dim3 trD(DIMM/32, DIMM/32);
    dim3 trF1(FFN/32, DIMM/32);
    dim3 trF2(DIMM/32, FFN/32);
    dim3 gP(DIMM/128, M1/128);
    dim3 gC(DIMM/128, MC/128);
    dim3 gF1(FFN/128, M1/128);
    dim3 gF2(DIMM/128, M1/128);
    dim3 gA(SS/64, HEADS, BB);

    // ---- pre-pass ----
    k_tr<<<trD,  trb>>>(sa_wq, wt + WT_Q,  DIMM, DIMM);
    k_tr<<<trD,  trb>>>(sa_wk, wt + WT_K,  DIMM, DIMM);
    k_tr<<<trD,  trb>>>(sa_wv, wt + WT_V,  DIMM, DIMM);
    k_tr<<<trD,  trb>>>(sa_wo, wt + WT_O,  DIMM, DIMM);
    k_tr<<<trD,  trb>>>(ca_wq, wt + WT_CQ, DIMM, DIMM);
    k_tr<<<trD,  trb>>>(ca_wk, wt + WT_CK, DIMM, DIMM);
    k_tr<<<trD,  trb>>>(ca_wv, wt + WT_CV, DIMM, DIMM);
    k_tr<<<trD,  trb>>>(ca_wo, wt + WT_CO, DIMM, DIMM);
    k_tr<<<trF1, trb>>>(w1,    wt + WT_F1, DIMM, FFN);
    k_tr<<<trF2, trb>>>(w2,    wt + WT_F2, FFN,  DIMM);
    k_tohalf<<<(MC*DIMM + 255)/256, blk>>>(context, ctxh, MC*DIMM);
    k_embed<<<(BB*6*DIMM + 255)/256, blk>>>(modu, e, em);
    k_ropetab<<<(SS*64 + 255)/256, blk>>>(fcos, fsin, cb, sb);

    // ---- self attention ----
    k_ln<<<M1, blk>>>(x, em + 1*DIMM, em + 0*DIMM, 1, xn);
    k_gemm_h<0,float><<<gP, blk>>>(xn, wt + WT_Q, sa_bq, nullptr, nullptr, tmp, M1, DIMM, DIMM);
    k_rms_t<<<M1, blk>>>(tmp, sa_nq, qh, SS, 1, QSC);
    k_gemm_h<0,float><<<gP, blk>>>(xn, wt + WT_K, sa_bk, nullptr, nullptr, tmp, M1, DIMM, DIMM);
    k_rms_t<<<M1, blk>>>(tmp, sa_nk, kh, SS, 1, 1.f);
    k_gemm_h<0,__half><<<gP, blk>>>(xn, wt + WT_V, sa_bv, nullptr, nullptr, vhp, M1, DIMM, DIMM);
    k_attn_h<<<gA, 128, ATTN_H_SMEM>>>(qh, kh, vhp, y, SS);
    k_gemm_h<3,float><<<gP, blk>>>(y, wt + WT_O, sa_bo, x, em + 2*DIMM, xb, M1, DIMM, DIMM);

    // ---- cross attention ----
    k_ln<<<M1, blk>>>(xb, n3_w, n3_b, 0, xn);
    k_gemm_h<0,float><<<gP, blk>>>(xn, wt + WT_CQ, ca_bq, nullptr, nullptr, tmp, M1, DIMM, DIMM);
    k_rms_t<<<M1, blk>>>(tmp, ca_nq, qh, SS, 0, QSC);
    k_gemm_h<0,float><<<gC, blk>>>(ctxh, wt + WT_CK, ca_bk, nullptr, nullptr, tmp, MC, DIMM, DIMM);
    k_rms_t<<<MC, blk>>>(tmp, ca_nk, kh, CTX, 0, 1.f);
    k_gemm_h<0,__half><<<gC, blk>>>(ctxh, wt + WT_CV, ca_bv, nullptr, nullptr, vhp, MC, DIMM, DIMM);
    k_attn_h<<<gA, 128, ATTN_H_SMEM>>>(qh, kh, vhp, y, CTX);
    k_gemm_h<2,float><<<gP, blk>>>(y, wt + WT_CO, ca_bo, xb, nullptr, xb, M1, DIMM, DIMM);

    // ---- FFN ----
    k_ln<<<M1, blk>>>(xb, em + 4*DIMM, em + 3*DIMM, 1, xn);
    k_gemm_h<1,__half><<<gF1, blk>>>(xn, wt + WT_F1, b1, nullptr, nullptr, h, M1, FFN, DIMM);
    k_gemm_h<3,float><<<gF2, blk>>>(h, wt + WT_F2, b2, xb, em + 5*DIMM, out, M1, DIMM, FFN);
}

// round 6
// speedup vs baseline: 7.2504x; 1.3535x over previous
#include <cuda_runtime.h>
#include <cuda_fp16.h>
#include <math.h>
#include <stddef.h>

// ---------------- problem constants ----------------
#define BB     2
#define SS     2048
#define DIMM   2048
#define HEADS  16
#define HD     128
#define FFN    8192
#define CTX    512
#define M1     (BB*SS)
#define MC     (BB*CTX)
#define EMSTR  (6*DIMM)
#define EPSF   1e-6f

// ---------------- device scratch ----------------
__device__ float g_em [BB*6*DIMM];
__device__ float g_cos[SS*(HD/2)];
__device__ float g_sin[SS*(HD/2)];
__device__ float g_x  [M1*DIMM];
__device__ float g_tmp[M1*DIMM];
__device__ __align__(128) __half g_qh [BB*HEADS*SS*HD];
__device__ __align__(128) __half g_kh [BB*HEADS*SS*HD];
__device__ __align__(128) __half g_vh [M1*DIMM];
__device__ __align__(128) __half g_xn [M1*DIMM];
__device__ __align__(128) __half g_y  [M1*DIMM];
__device__ __align__(128) __half g_h  [(size_t)M1*FFN];
__device__ __align__(128) __half g_ctx[MC*DIMM];
__device__ __align__(128) __half g_wt [64*1024*1024];

#define WT_Q   ((size_t)0)
#define WT_K   ((size_t)4*1024*1024)
#define WT_V   ((size_t)8*1024*1024)
#define WT_O   ((size_t)12*1024*1024)
#define WT_CQ  ((size_t)16*1024*1024)
#define WT_CK  ((size_t)20*1024*1024)
#define WT_CV  ((size_t)24*1024*1024)
#define WT_CO  ((size_t)28*1024*1024)
#define WT_F1  ((size_t)32*1024*1024)
#define WT_F2  ((size_t)48*1024*1024)

// ---------------- helpers ----------------
__device__ __forceinline__ void cp16(void* smem, const void* g) {
    unsigned s = (unsigned)__cvta_generic_to_shared(smem);
    asm volatile("cp.async.cg.shared.global [%0], [%1], 16;\n" :: "r"(s), "l"(g));
}
__device__ __forceinline__ void cp_commit() { asm volatile("cp.async.commit_group;\n"); }
__device__ __forceinline__ void cp_wait0()  { asm volatile("cp.async.wait_group 0;\n"); }
__device__ __forceinline__ void cp_wait1()  { asm volatile("cp.async.wait_group 1;\n"); }

__device__ __forceinline__ void mma16816(float* d, const unsigned* a, const unsigned* b) {
    asm volatile(
        "mma.sync.aligned.m16n8k16.row.col.f32.f16.f16.f32 "
        "{%0,%1,%2,%3}, {%4,%5,%6,%7}, {%8,%9}, {%0,%1,%2,%3};\n"
        : "+f"(d[0]), "+f"(d[1]), "+f"(d[2]), "+f"(d[3])
        : "r"(a[0]), "r"(a[1]), "r"(a[2]), "r"(a[3]), "r"(b[0]), "r"(b[1]));
}
__device__ __forceinline__ void ldsm4(unsigned* r, unsigned saddr) {
    asm volatile("ldmatrix.sync.aligned.m8n8.x4.shared.b16 {%0,%1,%2,%3}, [%4];\n"
                 : "=r"(r[0]), "=r"(r[1]), "=r"(r[2]), "=r"(r[3]) : "r"(saddr));
}
__device__ __forceinline__ void ldsm4t(unsigned& r0, unsigned& r1, unsigned& r2, unsigned& r3,
                                       unsigned saddr) {
    asm volatile("ldmatrix.sync.aligned.m8n8.x4.trans.shared.b16 {%0,%1,%2,%3}, [%4];\n"
                 : "=r"(r0), "=r"(r1), "=r"(r2), "=r"(r3) : "r"(saddr));
}
__device__ __forceinline__ unsigned packh2(float a, float b) {
    __half2 h = __floats2half2_rn(a, b);
    return *reinterpret_cast<unsigned*>(&h);
}

template<typename OT> __device__ __forceinline__ void stv(OT* p, float v);
template<> __device__ __forceinline__ void stv<float >(float*  p, float v) { *p = v; }
template<> __device__ __forceinline__ void stv<__half>(__half* p, float v) { *p = __float2half(v); }

// ---------------- small kernels ----------------
__global__ void k_embed(const float* __restrict__ mo, const float* __restrict__ e,
                        float* __restrict__ em) {
    int i = blockIdx.x*256 + threadIdx.x;
    if (i < BB*6*DIMM) em[i] = mo[i % EMSTR] + e[i];
}

__global__ void k_ropetab(const float* __restrict__ fc, const float* __restrict__ fs,
                          float* __restrict__ cb, float* __restrict__ sb) {
    int i = blockIdx.x*256 + threadIdx.x;
    if (i >= SS*64) return;
    int s = i >> 6, d = i & 63;
    int f = s >> 8, h = (s >> 4) & 15, w = s & 15;
    int row = (d < 22) ? f : ((d < 43) ? h : w);
    cb[i] = fc[row*64 + d];
    sb[i] = fs[row*64 + d];
}

__global__ void k_tohalf(const float* __restrict__ in, __half* __restrict__ out, int n) {
    int i = blockIdx.x*256 + threadIdx.x;
    if (i < n) out[i] = __float2half(in[i]);
}

__global__ void k_tr(const float* __restrict__ W, __half* __restrict__ WT, int K, int N) {
    __shared__ float t[32][33];
    int bx = blockIdx.x*32, by = blockIdx.y*32;
    int tx = threadIdx.x, ty = threadIdx.y;
#pragma unroll
    for (int i = 0; i < 4; i++)
        t[ty + 8*i][tx] = W[(size_t)(by + ty + 8*i)*N + bx + tx];
    __syncthreads();
#pragma unroll
    for (int i = 0; i < 4; i++)
        WT[(size_t)(bx + ty + 8*i)*K + by + tx] = __float2half(t[tx][ty + 8*i]);
}

__global__ void k_ln(const float* __restrict__ x, const float* __restrict__ scv,
                     const float* __restrict__ shv, int em_mode, __half* __restrict__ out) {
    __shared__ float buf[DIMM];
    __shared__ float red[256];
    __shared__ float s_m, s_inv;
    int row = blockIdx.x, tid = threadIdx.x;
    const float* xr = x + (size_t)row*DIMM;
    float ls = 0.f;
    for (int c = tid; c < DIMM; c += 256) { float v = xr[c]; buf[c] = v; ls += v; }
    red[tid] = ls; __syncthreads();
    for (int s2 = 128; s2 > 0; s2 >>= 1) { if (tid < s2) red[tid] += red[tid+s2]; __syncthreads(); }
    if (tid == 0) s_m = red[0] * (1.f/DIMM);
    __syncthreads();
    float m = s_m, lv = 0.f;
    for (int c = tid; c < DIMM; c += 256) { float d = buf[c]-m; lv += d*d; }
    red[tid] = lv; __syncthreads();
    for (int s2 = 128; s2 > 0; s2 >>= 1) { if (tid < s2) red[tid] += red[tid+s2]; __syncthreads(); }
    if (tid == 0) s_inv = rsqrtf(red[0]*(1.f/DIMM) + EPSF);
    __syncthreads();
    float inv = s_inv;
    int bo = (row >> 11) * EMSTR;
    __half* orow = out + (size_t)row*DIMM;
    for (int c = tid; c < DIMM; c += 256) {
        float sc, sh;
        if (em_mode) { sc = 1.f + scv[bo+c]; sh = shv[bo+c]; }
        else         { sc = scv[c];          sh = shv[c];    }
        orow[c] = __float2half((buf[c]-m)*inv*sc + sh);
    }
}

__global__ void k_rms_t(const float* __restrict__ in, const float* __restrict__ w,
                        __half* __restrict__ outT, int L, int do_rope, float oscale) {
    __shared__ float buf[DIMM];
    __shared__ float red[256];
    __shared__ float s_inv;
    int row = blockIdx.x, tid = threadIdx.x;
    int b = row / L, s = row % L;
    const float* xr = in + (size_t)row*DIMM;
    float ls = 0.f;
    for (int c = tid; c < DIMM; c += 256) { float v = xr[c]; buf[c] = v; ls += v*v; }
    red[tid] = ls; __syncthreads();
    for (int s2 = 128; s2 > 0; s2 >>= 1) { if (tid < s2) red[tid] += red[tid+s2]; __syncthreads(); }
    if (tid == 0) s_inv = rsqrtf(red[0]*(1.f/DIMM) + EPSF);
    __syncthreads();
    float inv = s_inv * oscale;
    if (do_rope) {
        for (int p = tid; p < DIMM/2; p += 256) {
            int hh = p >> 6, i = p & 63;
            float vr = buf[2*p]   * w[2*p]   * inv;
            float vi = buf[2*p+1] * w[2*p+1] * inv;
            float c = g_cos[s*64 + i], sn = g_sin[s*64 + i];
            size_t base = ((size_t)(b*HEADS + hh)*L + s) * HD;
            outT[base + 2*i]   = __float2half(vr*c - vi*sn);
            outT[base + 2*i+1] = __float2half(vr*sn + vi*c);
        }
    } else {
        for (int d = tid; d < DIMM; d += 256) {
            int hh = d >> 7, hd = d & 127;
            outT[((size_t)(b*HEADS + hh)*L + s)*HD + hd] = __float2half(buf[d]*inv*w[d]);
        }
    }
}

// ---------------- fp16 tensor-core GEMM v2 ----------------
// CTA 128x128x32, 4 warps (64x64 each), 3-stage cp.async ring, ldmatrix frags.
#define GLDH   40                      // halves per smem row (80B, conflict-free)
#define STG_A  (128*GLDH)              // halves per operand tile
#define STG_H  (2*STG_A)               // halves per stage (A+B)
#define GEMM_SMEM (3*STG_H*2)          // bytes = 61440
template<int EPI, typename OT>
__global__ __launch_bounds__(128, 2)
void k_gemm2(const __half* __restrict__ A, const __half* __restrict__ Bt,
             const float* __restrict__ bias, const float* __restrict__ res,
             const float* __restrict__ gate, OT* __restrict__ C,
             int M, int N, int K) {
    extern __shared__ __half sm[];
    int tid = threadIdx.x;
    int w = tid >> 5, lane = tid & 31;
    int bm = blockIdx.y << 7, bn = blockIdx.x << 7;
    const __half* Ab = A  + (size_t)bm*K;
    const __half* Bb = Bt + (size_t)bn*K;

    int wm = (w >> 1)*64, wn = (w & 1)*64;
    int r = lane >> 2, cc = lane & 3;
    int mat = lane >> 3, lr = lane & 7;

    // ldmatrix per-lane byte offsets (within operand tile)
    unsigned aoff[4], boff[4];
#pragma unroll
    for (int mi = 0; mi < 4; mi++)
        aoff[mi] = ((wm + mi*16 + ((mat & 1) << 3) + lr)*GLDH + ((mat >> 1) << 3)) * 2;
#pragma unroll
    for (int nj = 0; nj < 4; nj++)
        boff[nj] = ((wn + nj*16 + ((mat >> 1) << 3) + lr)*GLDH + ((mat & 1) << 3)) * 2;

    float acc[4][8][4];
#pragma unroll
    for (int i = 0; i < 4; i++)
#pragma unroll
        for (int j = 0; j < 8; j++)
#pragma unroll
            for (int t = 0; t < 4; t++) acc[i][j][t] = 0.f;

    auto stage = [&](int s, int kt) {
        __half* As = sm + s*STG_H;
        __half* Bs = As + STG_A;
        int k0 = kt*32;
#pragma unroll
        for (int i2 = 0; i2 < 4; i2++) {
            int ch = tid + i2*128;          // 0..511
            int row = ch >> 2, sg = ch & 3;
            cp16(&As[row*GLDH + sg*8], Ab + (size_t)row*K + k0 + sg*8);
            cp16(&Bs[row*GLDH + sg*8], Bb + (size_t)row*K + k0 + sg*8);
        }
        cp_commit();
    };

    int nk = K >> 5;
    stage(0, 0);
    stage(1, 1);
    for (int kt = 0; kt < nk; kt++) {
        cp_wait1();
        __syncthreads();
        if (kt + 2 < nk) stage((kt+2) % 3, kt+2);
        else             cp_commit();        // empty group keeps wait arithmetic uniform
        int st = kt % 3;
        unsigned abase = (unsigned)__cvta_generic_to_shared(sm + st*STG_H);
        unsigned bbase = abase + STG_A*2;
#pragma unroll
        for (int ks = 0; ks < 2; ks++) {
            unsigned af[4][4], bf[4][4];
#pragma unroll
            for (int mi = 0; mi < 4; mi++) ldsm4(af[mi], abase + aoff[mi] + ks*32);
#pragma unroll
            for (int nj = 0; nj < 4; nj++) ldsm4(bf[nj], bbase + boff[nj] + ks*32);
#pragma unroll
            for (int mi = 0; mi < 4; mi++)
#pragma unroll
                for (int nj = 0; nj < 4; nj++) {
                    mma16816(acc[mi][2*nj],     af[mi], &bf[nj][0]);
                    mma16816(acc[mi][2*nj + 1], af[mi], &bf[nj][2]);
                }
        }
        __syncthreads();
    }

    // epilogue
#pragma unroll
    for (int mi = 0; mi < 4; mi++) {
        int row0 = bm + wm + mi*16 + r;
#pragma unroll
        for (int nj = 0; nj < 8; nj++) {
            int col0 = bn + wn + nj*8 + 2*cc;
#pragma unroll
            for (int t = 0; t < 4; t++) {
                int rr  = row0 + ((t >> 1) ? 8 : 0);
                int col = col0 + (t & 1);
                float v = acc[mi][nj][t] + bias[col];
                if (EPI == 1) {
                    float u = v;
                    v = 0.5f*u*(1.f + tanhf(0.7978845608028654f*(u + 0.044715f*u*u*u)));
                }
                if (EPI == 2) v += res[(size_t)rr*N + col];
                if (EPI == 3) v = res[(size_t)rr*N + col] + v * gate[(rr >> 11)*EMSTR + col];
                stv(&C[(size_t)rr*N + col], v);
            }
        }
    }
}

// ---------------- fp16 flash attention (unchanged from R5) ----------------
#define AT_LDS 136
#define KVSZ   (64*AT_LDS)
#define ATTN_H_SMEM (4*KVSZ*2)
__global__ __launch_bounds__(128)
void k_attn_h(const __half* __restrict__ qt, const __half* __restrict__ kt,
              const __half* __restrict__ vh, __half* __restrict__ y, int Lk) {
    extern __shared__ __half smh[];
    __half* Kb = smh;
    __half* Vb = smh + 2*KVSZ;

    int tid = threadIdx.x;
    int w = tid >> 5, lane = tid & 31;
    int r = lane >> 2, cc = lane & 3;
    int qtile = blockIdx.x, hh = blockIdx.y, b = blockIdx.z;

    const __half* qb = qt + ((size_t)(b*HEADS + hh)*SS + qtile*64) * HD;
    const __half* kb = kt + (size_t)(b*HEADS + hh)*Lk*HD;
    const __half* vb = vh + (size_t)b*Lk*DIMM + hh*HD;

    auto stage_kv = [&](int st, int t2) {
        __half* Kd = Kb + st*KVSZ;
        __half* Vd = Vb + st*KVSZ;
#pragma unroll
        for (int i2 = 0; i2 < 8; i2++) {
            int ch = tid + i2*128;
            int row = ch >> 4, sg = ch & 15;
            cp16(&Kd[row*AT_LDS + sg*8], kb + (size_t)(t2*64 + row)*HD + sg*8);
            cp16(&Vd[row*AT_LDS + sg*8], vb + (size_t)(t2*64 + row)*DIMM + sg*8);
        }
        cp_commit();
    };

    {
        __half* Qd = Kb + KVSZ;
#pragma unroll
        for (int i2 = 0; i2 < 8; i2++) {
            int ch = tid + i2*128;
            int row = ch >> 4, sg = ch & 15;
            cp16(&Qd[row*AT_LDS + sg*8], qb + (size_t)row*HD + sg*8);
        }
        stage_kv(0, 0);
    }
    cp_wait0();
    __syncthreads();

    unsigned afrq[8][4];
    {
        const __half* Qs = Kb + KVSZ;
#pragma unroll
        for (int kc = 0; kc < 8; kc++) {
            int row = w*16 + r, col = kc*16 + 2*cc;
            afrq[kc][0] = *(const unsigned*)&Qs[row*AT_LDS + col];
            afrq[kc][1] = *(const unsigned*)&Qs[(row+8)*AT_LDS + col];
            afrq[kc][2] = *(const unsigned*)&Qs[row*AT_LDS + col + 8];
            afrq[kc][3] = *(const unsigned*)&Qs[(row+8)*AT_LDS + col + 8];
        }
    }

    float acc[16][4];
#pragma unroll
    for (int i = 0; i < 16; i++)
#pragma unroll
        for (int t = 0; t < 4; t++) acc[i][t] = 0.f;
    float m0 = -1e30f, m1 = -1e30f, l0 = 0.f, l1 = 0.f;

    int ntiles = Lk >> 6;
    for (int t2 = 0; t2 < ntiles; t2++) {
        __syncthreads();
        if (t2 + 1 < ntiles) { stage_kv((t2+1) & 1, t2+1); cp_wait1(); }
        else                 { cp_wait0(); }
        __syncthreads();
        const __half* Ks = Kb + (t2&1)*KVSZ;
        const __half* Vs = Vb + (t2&1)*KVSZ;

        float sacc[8][4];
#pragma unroll
        for (int nb = 0; nb < 8; nb++)
#pragma unroll
            for (int t = 0; t < 4; t++) sacc[nb][t] = 0.f;
#pragma unroll
        for (int kc = 0; kc < 8; kc++) {
            unsigned bfr[8][2];
            int col = kc*16 + 2*cc;
#pragma unroll
            for (int nb = 0; nb < 8; nb++) {
                int krow = nb*8 + r;
                bfr[nb][0] = *(const unsigned*)&Ks[krow*AT_LDS + col];
                bfr[nb][1] = *(const unsigned*)&Ks[krow*AT_LDS + col + 8];
            }
#pragma unroll
            for (int nb = 0; nb < 8; nb++) mma16816(sacc[nb], afrq[kc], bfr[nb]);
        }

        float mx0 = -1e30f, mx1 = -1e30f;
#pragma unroll
        for (int nb = 0; nb < 8; nb++) {
            mx0 = fmaxf(mx0, fmaxf(sacc[nb][0], sacc[nb][1]));
            mx1 = fmaxf(mx1, fmaxf(sacc[nb][2], sacc[nb][3]));
        }
        mx0 = fmaxf(mx0, __shfl_xor_sync(0xffffffffu, mx0, 1));
        mx0 = fmaxf(mx0, __shfl_xor_sync(0xffffffffu, mx0, 2));
        mx1 = fmaxf(mx1, __shfl_xor_sync(0xffffffffu, mx1, 1));
        mx1 = fmaxf(mx1, __shfl_xor_sync(0xffffffffu, mx1, 2));
        float mn0 = fmaxf(m0, mx0), mn1 = fmaxf(m1, mx1);
        float esc0 = __expf(m0 - mn0), esc1 = __expf(m1 - mn1);
        m0 = mn0; m1 = mn1;
        float ls0 = 0.f, ls1 = 0.f;
#pragma unroll
        for (int nb = 0; nb < 8; nb++) {
            sacc[nb][0] = __expf(sacc[nb][0] - mn0); ls0 += sacc[nb][0];
            sacc[nb][1] = __expf(sacc[nb][1] - mn0); ls0 += sacc[nb][1];
            sacc[nb][2] = __expf(sacc[nb][2] - mn1); ls1 += sacc[nb][2];
            sacc[nb][3] = __expf(sacc[nb][3] - mn1); ls1 += sacc[nb][3];
        }
        ls0 += __shfl_xor_sync(0xffffffffu, ls0, 1);
        ls0 += __shfl_xor_sync(0xffffffffu, ls0, 2);
        ls1 += __shfl_xor_sync(0xffffffffu, ls1, 1);
        ls1 += __shfl_xor_sync(0xffffffffu, ls1, 2);
        l0 = l0*esc0 + ls0;
        l1 = l1*esc1 + ls1;

        unsigned pf[4][4];
#pragma unroll
        for (int kc = 0; kc < 4; kc++) {
            pf[kc][0] = packh2(sacc[2*kc][0],   sacc[2*kc][1]);
            pf[kc][1] = packh2(sacc[2*kc][2],   sacc[2*kc][3]);
            pf[kc][2] = packh2(sacc[2*kc+1][0], sacc[2*kc+1][1]);
            pf[kc][3] = packh2(sacc[2*kc+1][2], sacc[2*kc+1][3]);
        }
#pragma unroll
        for (int nb = 0; nb < 16; nb++) {
            acc[nb][0] *= esc0; acc[nb][1] *= esc0;
            acc[nb][2] *= esc1; acc[nb][3] *= esc1;
        }

        unsigned vbase = (unsigned)__cvta_generic_to_shared(Vs);
        int lrow = (lane & 7) + ((lane >> 3) & 1)*8;
        int lcol = (lane >> 4)*8;
#pragma unroll
        for (int np = 0; np < 8; np++) {
#pragma unroll
            for (int kc = 0; kc < 4; kc++) {
                unsigned r0, r1, r2, r3;
                unsigned addr = vbase + (unsigned)(((kc*16 + lrow)*AT_LDS + np*16 + lcol)*2);
                ldsm4t(r0, r1, r2, r3, addr);
                unsigned b0[2] = {r0, r1};
                unsigned b1[2] = {r2, r3};
                mma16816(acc[np*2],     pf[kc], b0);
                mma16816(acc[np*2 + 1], pf[kc], b1);
            }
        }
    }

    float inv0 = 1.f/l0, inv1 = 1.f/l1;
    int row0 = qtile*64 + w*16 + r;
    __half* yb = y + (size_t)b*SS*DIMM + hh*HD;
#pragma unroll
    for (int nb = 0; nb < 16; nb++) {
        int col = nb*8 + 2*cc;
        __half2 h0 = __floats2half2_rn(acc[nb][0]*inv0, acc[nb][1]*inv0);
        __half2 h1 = __floats2half2_rn(acc[nb][2]*inv1, acc[nb][3]*inv1);
        *(__half2*)&yb[(size_t)row0*DIMM + col]     = h0;
        *(__half2*)&yb[(size_t)(row0+8)*DIMM + col] = h1;
    }
}

// ---------------- host ----------------
extern "C" void kernel_launch(void* const* d_in, const int* in_sizes, int n_in,
                              void* d_out, int out_size) {
    const float* x       = (const float*)d_in[0];
    const float* e       = (const float*)d_in[1];
    const float* context = (const float*)d_in[2];
    const float* fcos    = (const float*)d_in[3];
    const float* fsin    = (const float*)d_in[4];
    const float* modu    = (const float*)d_in[5];
    const float* sa_wq = (const float*)d_in[6];  const float* sa_bq = (const float*)d_in[7];
    const float* sa_wk = (const float*)d_in[8];  const float* sa_bk = (const float*)d_in[9];
    const float* sa_wv = (const float*)d_in[10]; const float* sa_bv = (const float*)d_in[11];
    const float* sa_wo = (const float*)d_in[12]; const float* sa_bo = (const float*)d_in[13];
    const float* sa_nq = (const float*)d_in[14]; const float* sa_nk = (const float*)d_in[15];
    const float* ca_wq = (const float*)d_in[16]; const float* ca_bq = (const float*)d_in[17];
    const float* ca_wk = (const float*)d_in[18]; const float* ca_bk = (const float*)d_in[19];
    const float* ca_wv = (const float*)d_in[20]; const float* ca_bv = (const float*)d_in[21];
    const float* ca_wo = (const float*)d_in[22]; const float* ca_bo = (const float*)d_in[23];
    const float* ca_nq = (const float*)d_in[24]; const float* ca_nk = (const float*)d_in[25];
    const float* n3_w  = (const float*)d_in[26]; const float* n3_b  = (const float*)d_in[27];
    const float* w1    = (const float*)d_in[28]; const float* b1    = (const float*)d_in[29];
    const float* w2    = (const float*)d_in[30]; const float* b2    = (const float*)d_in[31];
    float* out = (float*)d_out;

    float *em, *cb, *sb, *xb, *tmp;
    __half *qh, *kh, *vhp, *xn, *y, *h, *ctxh, *wt;
    cudaGetSymbolAddress((void**)&em,   g_em);
    cudaGetSymbolAddress((void**)&cb,   g_cos);
    cudaGetSymbolAddress((void**)&sb,   g_sin);
    cudaGetSymbolAddress((void**)&xb,   g_x);
    cudaGetSymbolAddress((void**)&tmp,  g_tmp);
    cudaGetSymbolAddress((void**)&qh,   g_qh);
    cudaGetSymbolAddress((void**)&kh,   g_kh);
    cudaGetSymbolAddress((void**)&vhp,  g_vh);
    cudaGetSymbolAddress((void**)&xn,   g_xn);
    cudaGetSymbolAddress((void**)&y,    g_y);
    cudaGetSymbolAddress((void**)&h,    g_h);
    cudaGetSymbolAddress((void**)&ctxh, g_ctx);
    cudaGetSymbolAddress((void**)&wt,   g_wt);

    cudaFuncSetAttribute(k_attn_h, cudaFuncAttributeMaxDynamicSharedMemorySize, ATTN_H_SMEM);
    cudaFuncSetAttribute(k_gemm2<0,float>,  cudaFuncAttributeMaxDynamicSharedMemorySize, GEMM_SMEM);
    cudaFuncSetAttribute(k_gemm2<0,__half>, cudaFuncAttributeMaxDynamicSharedMemorySize, GEMM_SMEM);
    cudaFuncSetAttribute(k_gemm2<1,__half>, cudaFuncAttributeMaxDynamicSharedMemorySize, GEMM_SMEM);
    cudaFuncSetAttribute(k_gemm2<2,float>,  cudaFuncAttributeMaxDynamicSharedMemorySize, GEMM_SMEM);
    cudaFuncSetAttribute(k_gemm2<3,float>,  cudaFuncAttributeMaxDynamicSharedMemorySize, GEMM_SMEM);

    const float QSC = 0.08838834764831845f;  // 1/sqrt(128)

    dim3 blk(256);
    dim3 gblk(128);
    dim3 trb(32, 8);
    dim3 trD(DIMM/32, DIMM/32);
    dim3 trF1(FFN/32, DIMM/32);
    dim3 trF2(DIMM/32, FFN/32);
    dim3 gP(DIMM/128, M1/128);
    dim3 gC(DIMM/128, MC/128);
    dim3 gF1(FFN/128, M1/128);
    dim3 gF2(DIMM/128, M1/128);
    dim3 gA(SS/64, HEADS, BB);

    // ---- pre-pass ----
    k_tr<<<trD,  trb>>>(sa_wq, wt + WT_Q,  DIMM, DIMM);
    k_tr<<<trD,  trb>>>(sa_wk, wt + WT_K,  DIMM, DIMM);
    k_tr<<<trD,  trb>>>(sa_wv, wt + WT_V,  DIMM, DIMM);
    k_tr<<<trD,  trb>>>(sa_wo, wt + WT_O,  DIMM, DIMM);
    k_tr<<<trD,  trb>>>(ca_wq, wt + WT_CQ, DIMM, DIMM);
    k_tr<<<trD,  trb>>>(ca_wk, wt + WT_CK, DIMM, DIMM);
    k_tr<<<trD,  trb>>>(ca_wv, wt + WT_CV, DIMM, DIMM);
    k_tr<<<trD,  trb>>>(ca_wo, wt + WT_CO, DIMM, DIMM);
    k_tr<<<trF1, trb>>>(w1,    wt + WT_F1, DIMM, FFN);
    k_tr<<<trF2, trb>>>(w2,    wt + WT_F2, FFN,  DIMM);
    k_tohalf<<<(MC*DIMM + 255)/256, blk>>>(context, ctxh, MC*DIMM);
    k_embed<<<(BB*6*DIMM + 255)/256, blk>>>(modu, e, em);
    k_ropetab<<<(SS*64 + 255)/256, blk>>>(fcos, fsin, cb, sb);

    // ---- self attention ----
    k_ln<<<M1, blk>>>(x, em + 1*DIMM, em + 0*DIMM, 1, xn);
    k_gemm2<0,float><<<gP, gblk, GEMM_SMEM>>>(xn, wt + WT_Q, sa_bq, nullptr, nullptr, tmp, M1, DIMM, DIMM);
    k_rms_t<<<M1, blk>>>(tmp, sa_nq, qh, SS, 1, QSC);
    k_gemm2<0,float><<<gP, gblk, GEMM_SMEM>>>(xn, wt + WT_K, sa_bk, nullptr, nullptr, tmp, M1, DIMM, DIMM);
    k_rms_t<<<M1, blk>>>(tmp, sa_nk, kh, SS, 1, 1.f);
    k_gemm2<0,__half><<<gP, gblk, GEMM_SMEM>>>(xn, wt + WT_V, sa_bv, nullptr, nullptr, vhp, M1, DIMM, DIMM);
    k_attn_h<<<gA, 128, ATTN_H_SMEM>>>(qh, kh, vhp, y, SS);
    k_gemm2<3,float><<<gP, gblk, GEMM_SMEM>>>(y, wt + WT_O, sa_bo, x, em + 2*DIMM, xb, M1, DIMM, DIMM);

    // ---- cross attention ----
    k_ln<<<M1, blk>>>(xb, n3_w, n3_b, 0, xn);
    k_gemm2<0,float><<<gP, gblk, GEMM_SMEM>>>(xn, wt + WT_CQ, ca_bq, nullptr, nullptr, tmp, M1, DIMM, DIMM);
    k_rms_t<<<M1, blk>>>(tmp, ca_nq, qh, SS, 0, QSC);
    k_gemm2<0,float><<<gC, gblk, GEMM_SMEM>>>(ctxh, wt + WT_CK, ca_bk, nullptr, nullptr, tmp, MC, DIMM, DIMM);
    k_rms_t<<<MC, blk>>>(tmp, ca_nk, kh, CTX, 0, 1.f);
    k_gemm2<0,__half><<<gC, gblk, GEMM_SMEM>>>(ctxh, wt + WT_CV, ca_bv, nullptr, nullptr, vhp, MC, DIMM, DIMM);
    k_attn_h<<<gA, 128, ATTN_H_SMEM>>>(qh, kh, vhp, y, CTX);
    k_gemm2<2,float><<<gP, gblk, GEMM_SMEM>>>(y, wt + WT_CO, ca_bo, xb, nullptr, xb, M1, DIMM, DIMM);

    // ---- FFN ----
    k_ln<<<M1, blk>>>(xb, em + 4*DIMM, em + 3*DIMM, 1, xn);
    k_gemm2<1,__half><<<gF1, gblk, GEMM_SMEM>>>(xn, wt + WT_F1, b1, nullptr, nullptr, h, M1, FFN, DIMM);
    k_gemm2<3,float><<<gF2, gblk, GEMM_SMEM>>>(h, wt + WT_F2, b2, xb, em + 5*DIMM, out, M1, DIMM, FFN);
}